// round 2
// baseline (speedup 1.0000x reference)
#include <cuda_runtime.h>
#include <cuda_bf16.h>
#include <math_constants.h>

// Problem constants
#define BB 8
#define NN 1024
#define TT 64
#define HH 64
#define ELEMS (BB*NN*TT)  // 524288

// Scratch (no allocations allowed)
__device__ float g_X[1024 * 1024];   // X[i*1024 + c], c in [0,512)=x1, [512,1024)=mask
__device__ float g_U[1024 * 1024];   // U[j*1024 + c]
__device__ float g_S[1024];          // column sums of adj
// Epilogue coefficient tables
__device__ float g_scd[512];         // [h][8] = r1,r1,r2,r2,r3,r3,r4,r4 (duplicated pairs)
__device__ float g_c12[256];         // [h][4] = c1,c1,c2,c2
__device__ float g_r56[128];         // [h][2] = r5,r6
__device__ float g_mt[65];           // sorted MLP breakpoints (1-based)
__device__ float g_msa[65];          // piecewise slope table
__device__ float g_msb[65];          // piecewise intercept table

// ---------- f32x2 helpers ----------
union U64 { unsigned long long u; float2 f; };

__device__ __forceinline__ unsigned long long ffma2(unsigned long long a,
                                                    unsigned long long b,
                                                    unsigned long long c) {
    unsigned long long d;
    asm("fma.rn.f32x2 %0, %1, %2, %3;" : "=l"(d) : "l"(a), "l"(b), "l"(c));
    return d;
}
__device__ __forceinline__ unsigned long long pack2(float x, float y) {
    U64 u; u.f = make_float2(x, y); return u.u;
}

// ---------------------------------------------------------------------------
// Kernel 1: fold all linear layers (h == 0 collapse) + build epilogue tables
// ---------------------------------------------------------------------------
__global__ void coef_kernel(const float* __restrict__ Win, const float* __restrict__ bin,
                            const float* __restrict__ Wgc, const float* __restrict__ bgc,
                            const float* __restrict__ Wlo, const float* __restrict__ blo,
                            const float* __restrict__ Wro, const float* __restrict__ prelu_a,
                            const float* __restrict__ Wo1, const float* __restrict__ bo1,
                            const float* __restrict__ Wo2, const float* __restrict__ bo2,
                            const float* __restrict__ bro) {
    __shared__ float sA[64], sC[64], sB[64];
    __shared__ float G[6][64];
    __shared__ float st[64], sa_s[64], sb_s[64], scz[64];
    __shared__ int   sp_s[64];
    __shared__ float srt_t[64], srt_a[64], srt_b[64];
    __shared__ int   srt_p[64];
    int t = threadIdx.x;  // 0..63
    // W_in shape (64, 66): col0 -> x1, col1 -> mask, rest hit h==0
    sA[t] = Win[t * 66 + 0];
    sC[t] = Win[t * 66 + 1];
    sB[t] = bin[t];
    __syncthreads();
    float g1 = 0, g2 = 0, g3 = 0, g4 = 0, g5 = 0, g6 = 0;
    for (int h = 0; h < 64; h++) {
        float w0 = Wgc[t * 128 + h];        // acts on z
        float w1 = Wgc[t * 128 + 64 + h];   // acts on zg
        g1 = fmaf(w0, sA[h], g1);
        g2 = fmaf(w0, sC[h], g2);
        g3 = fmaf(w0, sB[h], g3);
        g4 = fmaf(w1, sA[h], g4);
        g5 = fmaf(w1, sC[h], g5);
        g6 = fmaf(w1, sB[h], g6);
    }
    G[0][t] = g1;            // x1
    G[1][t] = g2;            // m
    G[2][t] = g4;            // u1
    G[3][t] = g5;            // u2
    G[4][t] = g6;            // s[j]
    G[5][t] = g3 + bgc[t];   // const
    __syncthreads();
    float r[6] = {0, 0, 0, 0, 0, 0};
    for (int o = 0; o < 64; o++) {
        float w = Wlo[t * 128 + o];  // second half of W_lo hits h==0
        r[0] = fmaf(w, G[0][o], r[0]);
        r[1] = fmaf(w, G[1][o], r[1]);
        r[2] = fmaf(w, G[2][o], r[2]);
        r[3] = fmaf(w, G[3][o], r[3]);
        r[4] = fmaf(w, G[4][o], r[4]);
        r[5] = fmaf(w, G[5][o], r[5]);
    }
    r[5] += blo[t];
    // duplicated-pair coefficient tables for f32x2 epilogue
    g_scd[t * 8 + 0] = r[0]; g_scd[t * 8 + 1] = r[0];
    g_scd[t * 8 + 2] = r[1]; g_scd[t * 8 + 3] = r[1];
    g_scd[t * 8 + 4] = r[2]; g_scd[t * 8 + 5] = r[2];
    g_scd[t * 8 + 6] = r[3]; g_scd[t * 8 + 7] = r[3];
    g_r56[t * 2 + 0] = r[4]; g_r56[t * 2 + 1] = r[5];
    float wr = Wro[t];           // W_ro[0, 0:64] (cols 64..127 hit h==0)
    float wp = wr;
    float wn = wr * prelu_a[0];
    float c1 = 0.5f * (wp + wn);
    float c2 = 0.5f * (wp - wn);
    g_c12[t * 4 + 0] = c1; g_c12[t * 4 + 1] = c1;
    g_c12[t * 4 + 2] = c2; g_c12[t * 4 + 3] = c2;

    // ---- piecewise-linear MLP tables ----
    // y = bo2 + sum_f Wo2[f] * relu(Wo1[f]*(x+bro) + bo1[f]), eval'd on x=acc
    float s1 = Wo1[t];
    float s2p = fmaf(s1, bro[0], bo1[t]);   // fold bro
    float s3 = Wo2[t];
    float tf, af, bf, cz = 0.f;
    int isP;
    if (s1 > 0.f)      { tf = -s2p / s1; isP = 1; af = s3 * s1; bf = s3 * s2p; }
    else if (s1 < 0.f) { tf = -s2p / s1; isP = 0; af = s3 * s1; bf = s3 * s2p; }
    else               { tf = CUDART_INF_F; isP = 0; af = 0.f; bf = 0.f;
                         cz = s3 * fmaxf(s2p, 0.f); }
    st[t] = tf; sa_s[t] = af; sb_s[t] = bf; sp_s[t] = isP; scz[t] = cz;
    __syncthreads();
    // rank (stable) -> sorted order
    int rank = 0;
    for (int g = 0; g < 64; g++) {
        float tg = st[g];
        if (tg < tf || (tg == tf && g < t)) rank++;
    }
    srt_t[rank] = tf; srt_a[rank] = af; srt_b[rank] = bf; srt_p[rank] = isP;
    __syncthreads();
    float C0 = bo2[0];
    for (int g = 0; g < 64; g++) C0 += scz[g];
    // tables for k = count of (sorted t <= x)
    for (int k = t; k <= 64; k += 64) {
        float A = 0.f, Bv = 0.f;
        for (int i = 0; i < 64; i++) {
            bool act = srt_p[i] ? (i < k) : (i >= k);
            if (act) { A += srt_a[i]; Bv += srt_b[i]; }
        }
        g_msa[k] = A;
        g_msb[k] = Bv + C0;
    }
    if (t < 64) g_mt[t + 1] = srt_t[t];
    if (t == 0) g_mt[0] = -CUDART_INF_F;
}

// ---------------------------------------------------------------------------
// Kernel 2: s[j] = sum_n adj[n, j]
// ---------------------------------------------------------------------------
__global__ void colsum_kernel(const float* __restrict__ adj) {
    int lane = threadIdx.x & 31;
    int grp  = threadIdx.x >> 5;      // 0..7
    int j = blockIdx.x * 32 + lane;
    float s = 0.f;
    for (int n = grp; n < 1024; n += 8) s += adj[n * 1024 + j];
    __shared__ float red[8][32];
    red[grp][lane] = s;
    __syncthreads();
    if (grp == 0) {
        float tot = 0.f;
        #pragma unroll
        for (int k = 0; k < 8; k++) tot += red[k][lane];
        g_S[j] = tot;
    }
}

// ---------------------------------------------------------------------------
// Kernel 3: build X[i, c]: cols [0,512)=x1, [512,1024)=mask
// ---------------------------------------------------------------------------
__global__ void buildX_kernel(const float* __restrict__ x, const int* __restrict__ mask,
                              const float* __restrict__ bfs) {
    int tid = blockIdx.x * 512 + threadIdx.x;  // 0 .. 524287
    int i = tid >> 9;          // node index (k-dim)
    int c = tid & 511;         // b*64 + t
    int b = c >> 6, t = c & 63;
    int src = b * (NN * TT) + i * TT + t;
    int m = mask[src];
    float bfs0 = bfs[0];
    float xv = x[src];
    g_X[i * 1024 + c]       = m ? xv : bfs0;
    g_X[i * 1024 + 512 + c] = (float)m;
}

// ---------------------------------------------------------------------------
// Kernel 4: U[j, c] = sum_i adj[i, j] * X[i, c]   (fp32 TN GEMM, f32x2 FMA)
// 64x64 tile, BK=16, 256 threads, 4x4 micro-tile, A stored duplicated in smem
// ---------------------------------------------------------------------------
__global__ __launch_bounds__(256) void sgemm_tn_kernel(const float* __restrict__ adj) {
    __shared__ float As[16][128];   // duplicated pairs: [k][2m]=[k][2m+1]=A[k][j0+m]
    __shared__ float Bs[16][64];
    int j0 = blockIdx.y * 64;
    int c0 = blockIdx.x * 64;
    int tx = threadIdx.x & 15;
    int ty = threadIdx.x >> 4;
    int lrow  = threadIdx.x >> 4;        // 0..15
    int lcol4 = (threadIdx.x & 15) * 4;  // 0..60

    unsigned long long acc[4][2];
    #pragma unroll
    for (int m = 0; m < 4; m++) { acc[m][0] = 0ULL; acc[m][1] = 0ULL; }

    const float* aptr = adj + (size_t)lrow * 1024 + j0 + lcol4;
    const float* bptr = g_X + (size_t)lrow * 1024 + c0 + lcol4;
    float4 a = *(const float4*)aptr;
    float4 b = *(const float4*)bptr;

    for (int k0 = 0; k0 < 1024; k0 += 16) {
        // store current tile
        float4 dlo = make_float4(a.x, a.x, a.y, a.y);
        float4 dhi = make_float4(a.z, a.z, a.w, a.w);
        *(float4*)&As[lrow][lcol4 * 2]     = dlo;
        *(float4*)&As[lrow][lcol4 * 2 + 4] = dhi;
        *(float4*)&Bs[lrow][lcol4] = b;
        __syncthreads();
        // prefetch next tile
        if (k0 + 16 < 1024) {
            aptr += 16 * 1024;
            bptr += 16 * 1024;
            a = *(const float4*)aptr;
            b = *(const float4*)bptr;
        }
        #pragma unroll
        for (int kk = 0; kk < 16; kk++) {
            ulonglong2 a01 = *(const ulonglong2*)&As[kk][ty * 8];     // (a0,a0),(a1,a1)
            ulonglong2 a23 = *(const ulonglong2*)&As[kk][ty * 8 + 4]; // (a2,a2),(a3,a3)
            ulonglong2 bv  = *(const ulonglong2*)&Bs[kk][tx * 4];     // (b0,b1),(b2,b3)
            acc[0][0] = ffma2(a01.x, bv.x, acc[0][0]);
            acc[0][1] = ffma2(a01.x, bv.y, acc[0][1]);
            acc[1][0] = ffma2(a01.y, bv.x, acc[1][0]);
            acc[1][1] = ffma2(a01.y, bv.y, acc[1][1]);
            acc[2][0] = ffma2(a23.x, bv.x, acc[2][0]);
            acc[2][1] = ffma2(a23.x, bv.y, acc[2][1]);
            acc[3][0] = ffma2(a23.y, bv.x, acc[3][0]);
            acc[3][1] = ffma2(a23.y, bv.y, acc[3][1]);
        }
        __syncthreads();
    }
    #pragma unroll
    for (int m = 0; m < 4; m++) {
        int j = j0 + ty * 4 + m;
        U64 p0, p1; p0.u = acc[m][0]; p1.u = acc[m][1];
        float4 v = make_float4(p0.f.x, p0.f.y, p1.f.x, p1.f.y);
        *(float4*)&g_U[(size_t)j * 1024 + c0 + tx * 4] = v;
    }
}

// ---------------------------------------------------------------------------
// Kernel 5: pointwise epilogue (f32x2 head + piecewise-linear MLP)
// ---------------------------------------------------------------------------
__global__ __launch_bounds__(256) void epilogue_kernel(
    const float* __restrict__ x, const int* __restrict__ mask,
    const float* __restrict__ bfs, float* __restrict__ out) {
    __shared__ float s_scd[512];
    __shared__ float s_c12[256];
    __shared__ float s_r56[128];
    __shared__ float s_mt[65], s_msa[65], s_msb[65];
    int tid = threadIdx.x;
    for (int i = tid; i < 512; i += 256) s_scd[i] = g_scd[i];
    s_c12[tid] = g_c12[tid];
    if (tid < 128) s_r56[tid] = g_r56[tid];
    if (tid < 65) { s_mt[tid] = g_mt[tid]; s_msa[tid] = g_msa[tid]; s_msb[tid] = g_msb[tid]; }
    __syncthreads();
    float bfs0 = bfs[0];

    int gid = blockIdx.x * 256 + tid;  // 0 .. 131071
    int e = gid * 4;
    int b = e >> 16;
    int rem = e & 65535;
    int j = rem >> 6;
    int tt = rem & 63;
    int c = b * 64 + tt;

    float4 xv = *(const float4*)&x[e];
    int4 mv = *(const int4*)&mask[e];
    const float* Ub = g_U + (size_t)j * 1024 + c;
    float4 u1v = *(const float4*)Ub;
    float4 u2v = *(const float4*)(Ub + 512);
    float sj = g_S[j];

    float x1a[4], mfa[4];
    x1a[0] = mv.x ? xv.x : bfs0; mfa[0] = (float)mv.x;
    x1a[1] = mv.y ? xv.y : bfs0; mfa[1] = (float)mv.y;
    x1a[2] = mv.z ? xv.z : bfs0; mfa[2] = (float)mv.z;
    x1a[3] = mv.w ? xv.w : bfs0; mfa[3] = (float)mv.w;

    unsigned long long x1p[2] = { pack2(x1a[0], x1a[1]), pack2(x1a[2], x1a[3]) };
    unsigned long long mfp[2] = { pack2(mfa[0], mfa[1]), pack2(mfa[2], mfa[3]) };
    unsigned long long u1p[2] = { pack2(u1v.x, u1v.y), pack2(u1v.z, u1v.w) };
    unsigned long long u2p[2] = { pack2(u2v.x, u2v.y), pack2(u2v.z, u2v.w) };

    unsigned long long acc2[2] = { 0ULL, 0ULL };
    #pragma unroll 4
    for (int h = 0; h < 64; h++) {
        ulonglong2 r12 = *(const ulonglong2*)&s_scd[h * 8];     // (r1,r1),(r2,r2)
        ulonglong2 r34 = *(const ulonglong2*)&s_scd[h * 8 + 4]; // (r3,r3),(r4,r4)
        float2 r56v = *(const float2*)&s_r56[h * 2];
        ulonglong2 cc = *(const ulonglong2*)&s_c12[h * 4];      // (c1,c1),(c2,c2)
        float base = fmaf(r56v.x, sj, r56v.y);
        unsigned long long base2 = pack2(base, base);
        #pragma unroll
        for (int q = 0; q < 2; q++) {
            unsigned long long v =
                ffma2(r12.x, x1p[q],
                ffma2(r12.y, mfp[q],
                ffma2(r34.x, u1p[q],
                ffma2(r34.y, u2p[q], base2))));
            unsigned long long av = v & 0x7fffffff7fffffffULL;  // |v| both halves
            acc2[q] = ffma2(cc.x, v, acc2[q]);
            acc2[q] = ffma2(cc.y, av, acc2[q]);
        }
    }

    float accs[4];
    { U64 p; p.u = acc2[0]; accs[0] = p.f.x; accs[1] = p.f.y; }
    { U64 p; p.u = acc2[1]; accs[2] = p.f.x; accs[3] = p.f.y; }

    float res[4];
    #pragma unroll
    for (int q = 0; q < 4; q++) {
        float xs = accs[q];
        int k = 0;
        #pragma unroll
        for (int step = 64; step > 0; step >>= 1) {
            if (k + step <= 64 && s_mt[k + step] <= xs) k += step;
        }
        res[q] = fmaf(s_msa[k], xs, s_msb[k]);
    }
    *(float4*)&out[e] = make_float4(res[0], res[1], res[2], res[3]);
}

// ---------------------------------------------------------------------------
// Launch
// ---------------------------------------------------------------------------
extern "C" void kernel_launch(void* const* d_in, const int* in_sizes, int n_in,
                              void* d_out, int out_size) {
    const float* x      = (const float*)d_in[0];
    const int*   mask   = (const int*)  d_in[1];
    // d_in[2] = W_fs (unused: multiplies h == 0)
    const float* b_fs   = (const float*)d_in[3];
    const float* W_in   = (const float*)d_in[4];
    const float* b_in   = (const float*)d_in[5];
    const float* adj    = (const float*)d_in[6];
    const float* W_gc   = (const float*)d_in[7];
    const float* b_gc   = (const float*)d_in[8];
    const float* W_lo   = (const float*)d_in[9];
    const float* b_lo   = (const float*)d_in[10];
    const float* prelua = (const float*)d_in[11];
    const float* W_ro   = (const float*)d_in[12];
    const float* b_ro   = (const float*)d_in[13];
    const float* W_o1   = (const float*)d_in[14];
    const float* b_o1   = (const float*)d_in[15];
    const float* W_o2   = (const float*)d_in[16];
    const float* b_o2   = (const float*)d_in[17];
    float* out = (float*)d_out;

    coef_kernel<<<1, 64>>>(W_in, b_in, W_gc, b_gc, W_lo, b_lo, W_ro, prelua,
                           W_o1, b_o1, W_o2, b_o2, b_ro);
    colsum_kernel<<<32, 256>>>(adj);
    buildX_kernel<<<1024, 512>>>(x, mask, b_fs);
    dim3 ggrid(16, 16);
    sgemm_tn_kernel<<<ggrid, 256>>>(adj);
    epilogue_kernel<<<ELEMS / 4 / 256, 256>>>(x, mask, b_fs, out);
}

// round 4
// speedup vs baseline: 1.6050x; 1.6050x over previous
#include <cuda_runtime.h>
#include <cuda_bf16.h>
#include <math_constants.h>
#include <cstdint>

// Problem constants
#define BB 8
#define NN 1024
#define TT 64
#define ELEMS (BB*NN*TT)  // 524288

// Scratch (no allocations allowed)
__device__ __nv_bfloat16 g_Ah[1024 * 1024];  // A[m=j][k=i] = adj[i][j], hi part
__device__ __nv_bfloat16 g_Al[1024 * 1024];  // lo part
__device__ __nv_bfloat16 g_Bh[1024 * 1024];  // B[n=c][k=i] = X[i][c], hi part
__device__ __nv_bfloat16 g_Bl[1024 * 1024];  // lo part
__device__ float g_U[1024 * 1024];           // split-K partial 0
__device__ float g_U2[1024 * 1024];          // split-K partial 1
__device__ float g_S[1024];                  // column sums of adj
// Epilogue coefficient tables
__device__ float g_scd[512];         // [h][8] = r1,r1,r2,r2,r3,r3,r4,r4
__device__ float g_c12[256];         // [h][4] = c1,c1,c2,c2
__device__ float g_r56[128];         // [h][2] = r5,r6
__device__ float g_mt[65];           // sorted MLP breakpoints (1-based)
__device__ float g_msa[65];          // piecewise slope table
__device__ float g_msb[65];          // piecewise intercept table

// ---------- helpers ----------
union U64 { unsigned long long u; float2 f; };

__device__ __forceinline__ unsigned long long ffma2(unsigned long long a,
                                                    unsigned long long b,
                                                    unsigned long long c) {
    unsigned long long d;
    asm("fma.rn.f32x2 %0, %1, %2, %3;" : "=l"(d) : "l"(a), "l"(b), "l"(c));
    return d;
}
__device__ __forceinline__ unsigned long long pack2(float x, float y) {
    U64 u; u.f = make_float2(x, y); return u.u;
}
__device__ __forceinline__ uint32_t smem_u32(const void* p) {
    uint32_t a;
    asm("{ .reg .u64 t; cvta.to.shared.u64 t, %1; cvt.u32.u64 %0, t; }" : "=r"(a) : "l"(p));
    return a;
}
__device__ __forceinline__ void cpasync16(uint32_t s, const void* g) {
    asm volatile("cp.async.cg.shared.global [%0], [%1], 16;" :: "r"(s), "l"(g));
}
#define CP_COMMIT() asm volatile("cp.async.commit_group;" ::: "memory")

__device__ __forceinline__ void ldm_x4(uint32_t& r0, uint32_t& r1, uint32_t& r2,
                                       uint32_t& r3, uint32_t a) {
    asm volatile("ldmatrix.sync.aligned.m8n8.x4.shared.b16 {%0,%1,%2,%3}, [%4];"
                 : "=r"(r0), "=r"(r1), "=r"(r2), "=r"(r3) : "r"(a));
}
__device__ __forceinline__ void ldm_x2(uint32_t& r0, uint32_t& r1, uint32_t a) {
    asm volatile("ldmatrix.sync.aligned.m8n8.x2.shared.b16 {%0,%1}, [%2];"
                 : "=r"(r0), "=r"(r1) : "r"(a));
}
__device__ __forceinline__ void mma_bf16(float& c0, float& c1, float& c2, float& c3,
                                         uint32_t a0, uint32_t a1, uint32_t a2, uint32_t a3,
                                         uint32_t b0, uint32_t b1) {
    asm volatile(
        "mma.sync.aligned.m16n8k16.row.col.f32.bf16.bf16.f32 "
        "{%0,%1,%2,%3}, {%4,%5,%6,%7}, {%8,%9}, {%0,%1,%2,%3};"
        : "+f"(c0), "+f"(c1), "+f"(c2), "+f"(c3)
        : "r"(a0), "r"(a1), "r"(a2), "r"(a3), "r"(b0), "r"(b1));
}

// ---------------------------------------------------------------------------
// Kernel 1: fold all linear layers (h == 0 collapse) + build epilogue tables
// ---------------------------------------------------------------------------
__global__ void coef_kernel(const float* __restrict__ Win, const float* __restrict__ bin,
                            const float* __restrict__ Wgc, const float* __restrict__ bgc,
                            const float* __restrict__ Wlo, const float* __restrict__ blo,
                            const float* __restrict__ Wro, const float* __restrict__ prelu_a,
                            const float* __restrict__ Wo1, const float* __restrict__ bo1,
                            const float* __restrict__ Wo2, const float* __restrict__ bo2,
                            const float* __restrict__ bro) {
    __shared__ float sA[64], sC[64], sB[64];
    __shared__ float G[6][64];
    __shared__ float st[64], scz[64];
    __shared__ float srt_t[64], srt_a[64], srt_b[64];
    __shared__ int   srt_p[64];
    int t = threadIdx.x;  // 0..63
    sA[t] = Win[t * 66 + 0];
    sC[t] = Win[t * 66 + 1];
    sB[t] = bin[t];
    __syncthreads();
    float g1 = 0, g2 = 0, g3 = 0, g4 = 0, g5 = 0, g6 = 0;
    for (int h = 0; h < 64; h++) {
        float w0 = Wgc[t * 128 + h];
        float w1 = Wgc[t * 128 + 64 + h];
        g1 = fmaf(w0, sA[h], g1);
        g2 = fmaf(w0, sC[h], g2);
        g3 = fmaf(w0, sB[h], g3);
        g4 = fmaf(w1, sA[h], g4);
        g5 = fmaf(w1, sC[h], g5);
        g6 = fmaf(w1, sB[h], g6);
    }
    G[0][t] = g1; G[1][t] = g2; G[2][t] = g4;
    G[3][t] = g5; G[4][t] = g6; G[5][t] = g3 + bgc[t];
    __syncthreads();
    float r[6] = {0, 0, 0, 0, 0, 0};
    for (int o = 0; o < 64; o++) {
        float w = Wlo[t * 128 + o];
        r[0] = fmaf(w, G[0][o], r[0]);
        r[1] = fmaf(w, G[1][o], r[1]);
        r[2] = fmaf(w, G[2][o], r[2]);
        r[3] = fmaf(w, G[3][o], r[3]);
        r[4] = fmaf(w, G[4][o], r[4]);
        r[5] = fmaf(w, G[5][o], r[5]);
    }
    r[5] += blo[t];
    g_scd[t * 8 + 0] = r[0]; g_scd[t * 8 + 1] = r[0];
    g_scd[t * 8 + 2] = r[1]; g_scd[t * 8 + 3] = r[1];
    g_scd[t * 8 + 4] = r[2]; g_scd[t * 8 + 5] = r[2];
    g_scd[t * 8 + 6] = r[3]; g_scd[t * 8 + 7] = r[3];
    g_r56[t * 2 + 0] = r[4]; g_r56[t * 2 + 1] = r[5];
    float wr = Wro[t];
    float wp = wr;
    float wn = wr * prelu_a[0];
    float c1 = 0.5f * (wp + wn);
    float c2 = 0.5f * (wp - wn);
    g_c12[t * 4 + 0] = c1; g_c12[t * 4 + 1] = c1;
    g_c12[t * 4 + 2] = c2; g_c12[t * 4 + 3] = c2;

    // piecewise-linear MLP tables
    float s1 = Wo1[t];
    float s2p = fmaf(s1, bro[0], bo1[t]);
    float s3 = Wo2[t];
    float tf, af, bf, cz = 0.f;
    int isP;
    if (s1 > 0.f)      { tf = -s2p / s1; isP = 1; af = s3 * s1; bf = s3 * s2p; }
    else if (s1 < 0.f) { tf = -s2p / s1; isP = 0; af = s3 * s1; bf = s3 * s2p; }
    else               { tf = CUDART_INF_F; isP = 0; af = 0.f; bf = 0.f;
                         cz = s3 * fmaxf(s2p, 0.f); }
    st[t] = tf; scz[t] = cz;
    __syncthreads();
    int rank = 0;
    for (int g = 0; g < 64; g++) {
        float tg = st[g];
        if (tg < tf || (tg == tf && g < t)) rank++;
    }
    srt_t[rank] = tf; srt_a[rank] = af; srt_b[rank] = bf; srt_p[rank] = isP;
    __syncthreads();
    float C0 = bo2[0];
    for (int g = 0; g < 64; g++) C0 += scz[g];
    for (int k = t; k <= 64; k += 64) {
        float A = 0.f, Bv = 0.f;
        for (int i = 0; i < 64; i++) {
            bool act = srt_p[i] ? (i < k) : (i >= k);
            if (act) { A += srt_a[i]; Bv += srt_b[i]; }
        }
        g_msa[k] = A;
        g_msb[k] = Bv + C0;
    }
    if (t < 64) g_mt[t + 1] = srt_t[t];
    if (t == 0) g_mt[0] = -CUDART_INF_F;
}

// ---------------------------------------------------------------------------
// Kernel 2: s[j] = sum_n adj[n, j]
// ---------------------------------------------------------------------------
__global__ void colsum_kernel(const float* __restrict__ adj) {
    int lane = threadIdx.x & 31;
    int grp  = threadIdx.x >> 5;
    int j = blockIdx.x * 32 + lane;
    float s = 0.f;
    for (int n = grp; n < 1024; n += 8) s += adj[n * 1024 + j];
    __shared__ float red[8][32];
    red[grp][lane] = s;
    __syncthreads();
    if (grp == 0) {
        float tot = 0.f;
        #pragma unroll
        for (int k = 0; k < 8; k++) tot += red[k][lane];
        g_S[j] = tot;
    }
}

// ---------------------------------------------------------------------------
// Kernel 3a: transpose + split adj -> Ah/Al bf16, layout [m=j][k=i]
// ---------------------------------------------------------------------------
__global__ void convertA_kernel(const float* __restrict__ adj) {
    __shared__ float tile[32][33];
    int tx = threadIdx.x, ty = threadIdx.y;  // 32 x 8
    int j0 = blockIdx.x * 32, i0 = blockIdx.y * 32;
    #pragma unroll
    for (int s = 0; s < 4; s++)
        tile[ty + 8 * s][tx] = adj[(i0 + ty + 8 * s) * 1024 + j0 + tx];
    __syncthreads();
    #pragma unroll
    for (int s = 0; s < 4; s++) {
        float v = tile[tx][ty + 8 * s];
        __nv_bfloat16 h = __float2bfloat16_rn(v);
        __nv_bfloat16 l = __float2bfloat16_rn(v - __bfloat162float(h));
        int idx = (j0 + ty + 8 * s) * 1024 + i0 + tx;
        g_Ah[idx] = h;
        g_Al[idx] = l;
    }
}

// ---------------------------------------------------------------------------
// Kernel 3b: build B[n=c][k=i] bf16 hi/lo from x, mask
//   c in [0,512): x1 = mask ? x : bfs0 ;  c in [512,1024): mask (exact, lo=0)
// ---------------------------------------------------------------------------
__global__ __launch_bounds__(256) void convertX_kernel(const float* __restrict__ x,
                                                       const int* __restrict__ mask,
                                                       const float* __restrict__ bfs) {
    __shared__ float sx[64][65];
    __shared__ float sm[64][65];
    int tid = threadIdx.x;
    int b = blockIdx.y, i0 = blockIdx.x * 64;
    int r = tid >> 2;
    int t4 = (tid & 3) * 16;
    int base = (b * 1024 + i0 + r) * 64 + t4;
    #pragma unroll
    for (int q = 0; q < 4; q++) {
        float4 v = *(const float4*)&x[base + q * 4];
        int4   m = *(const int4*)&mask[base + q * 4];
        sx[r][t4 + q * 4 + 0] = v.x; sx[r][t4 + q * 4 + 1] = v.y;
        sx[r][t4 + q * 4 + 2] = v.z; sx[r][t4 + q * 4 + 3] = v.w;
        sm[r][t4 + q * 4 + 0] = (float)m.x; sm[r][t4 + q * 4 + 1] = (float)m.y;
        sm[r][t4 + q * 4 + 2] = (float)m.z; sm[r][t4 + q * 4 + 3] = (float)m.w;
    }
    __syncthreads();
    float bfs0 = bfs[0];
    int t = tid >> 2;
    int i4 = (tid & 3) * 16;
    int c1 = b * 64 + t;
    __align__(16) __nv_bfloat16 hh[16], ll[16], mh[16];
    #pragma unroll
    for (int q = 0; q < 16; q++) {
        float mv = sm[i4 + q][t];
        float xv = sx[i4 + q][t];
        float x1 = (mv != 0.0f) ? xv : bfs0;
        __nv_bfloat16 h = __float2bfloat16_rn(x1);
        hh[q] = h;
        ll[q] = __float2bfloat16_rn(x1 - __bfloat162float(h));
        mh[q] = __float2bfloat16_rn(mv);
    }
    int row1 = c1 * 1024 + i0 + i4;
    *(uint4*)&g_Bh[row1]     = *(uint4*)&hh[0];
    *(uint4*)&g_Bh[row1 + 8] = *(uint4*)&hh[8];
    *(uint4*)&g_Bl[row1]     = *(uint4*)&ll[0];
    *(uint4*)&g_Bl[row1 + 8] = *(uint4*)&ll[8];
    int row2 = (512 + c1) * 1024 + i0 + i4;
    uint4 z = make_uint4(0, 0, 0, 0);
    *(uint4*)&g_Bh[row2]     = *(uint4*)&mh[0];
    *(uint4*)&g_Bh[row2 + 8] = *(uint4*)&mh[8];
    *(uint4*)&g_Bl[row2]     = z;
    *(uint4*)&g_Bl[row2 + 8] = z;
}

// ---------------------------------------------------------------------------
// Kernel 4: bf16 tensor-core GEMM (mma.sync m16n8k16), 3-pass split accum,
// split-K=2. U[j,c] = sum_i adj[i,j]*X[i,c] ≈ Ah·Bh + Ah·Bl + Al·Bh.
// Tile M=128 N=128, KC=32, 8 warps (warp tile 64x32), double-buffered cp.async.
// smem rows padded to 80B -> conflict-free ldmatrix.
// ---------------------------------------------------------------------------
#define KC 32
#define ROWB 80
#define BUFB 20480   // (128 A-rows + 128 B-rows) * 80

__global__ __launch_bounds__(256) void mma_kernel() {
    __shared__ __align__(16) char smem[2 * BUFB];
    int tid = threadIdx.x;
    int wid = tid >> 5, lane = tid & 31;
    int m0 = (blockIdx.x >> 3) * 128;
    int n0 = (blockIdx.x & 7) * 128;
    int kbase = blockIdx.y * 512;
    uint32_t sbase = smem_u32(smem);

    // per-thread cp.async mapping: 4 x 16B chunks per buffer fill
    int isB_[4]; uint32_t soff[4]; int goff[4];
    #pragma unroll
    for (int q = 0; q < 4; q++) {
        int c = tid + 256 * q;
        int isB = c >> 9;
        int row = (c >> 2) & 127;
        int col = c & 3;
        isB_[q] = isB;
        soff[q] = (isB ? 128 * ROWB : 0) + row * ROWB + col * 16;
        goff[q] = ((isB ? n0 : m0) + row) * 1024 + col * 8;
    }

    const __nv_bfloat16* Apass[3] = {g_Ah, g_Ah, g_Al};
    const __nv_bfloat16* Bpass[3] = {g_Bh, g_Bl, g_Bh};

    float acc[4][4][4];
    #pragma unroll
    for (int mt = 0; mt < 4; mt++)
        #pragma unroll
        for (int nt = 0; nt < 4; nt++)
            #pragma unroll
            for (int q = 0; q < 4; q++) acc[mt][nt][q] = 0.f;

    int warp_m = (wid >> 2) * 64;
    int warp_n = (wid & 3) * 32;
    // ldmatrix base addresses (chunk col added per k-step)
    uint32_t a_row_off = (warp_m + (lane & 15)) * ROWB + ((lane >> 4) & 1) * 16;
    uint32_t b_row_off = 128 * ROWB + (warp_n + (lane & 7)) * ROWB + ((lane >> 3) & 1) * 16;

    // prologue: load iteration 0 into buf 0
    {
        const __nv_bfloat16* Aar = Apass[0];
        const __nv_bfloat16* Bar = Bpass[0];
        #pragma unroll
        for (int q = 0; q < 4; q++) {
            const __nv_bfloat16* src = (isB_[q] ? Bar : Aar) + goff[q] + kbase;
            cpasync16(sbase + soff[q], src);
        }
        CP_COMMIT();
    }

    for (int it = 0; it < 48; it++) {
        int buf = it & 1;
        if (it + 1 < 48) {
            int p = (it + 1) >> 4;
            int k0 = kbase + ((it + 1) & 15) * KC;
            const __nv_bfloat16* Aar = Apass[p];
            const __nv_bfloat16* Bar = Bpass[p];
            uint32_t sb = sbase + (buf ^ 1) * BUFB;
            #pragma unroll
            for (int q = 0; q < 4; q++) {
                const __nv_bfloat16* src = (isB_[q] ? Bar : Aar) + goff[q] + k0;
                cpasync16(sb + soff[q], src);
            }
            CP_COMMIT();
            asm volatile("cp.async.wait_group 1;" ::: "memory");
        } else {
            asm volatile("cp.async.wait_group 0;" ::: "memory");
        }
        __syncthreads();

        uint32_t sb = sbase + buf * BUFB;
        #pragma unroll
        for (int ks = 0; ks < 2; ks++) {
            uint32_t b0[4], b1[4];
            uint32_t baddr = sb + b_row_off + ks * 32;
            #pragma unroll
            for (int nt = 0; nt < 4; nt++)
                ldm_x2(b0[nt], b1[nt], baddr + nt * 8 * ROWB);
            uint32_t aaddr = sb + a_row_off + ks * 32;
            #pragma unroll
            for (int mt = 0; mt < 4; mt++) {
                uint32_t a0, a1, a2, a3;
                ldm_x4(a0, a1, a2, a3, aaddr + mt * 16 * ROWB);
                #pragma unroll
                for (int nt = 0; nt < 4; nt++)
                    mma_bf16(acc[mt][nt][0], acc[mt][nt][1], acc[mt][nt][2], acc[mt][nt][3],
                             a0, a1, a2, a3, b0[nt], b1[nt]);
            }
        }
        __syncthreads();
    }

    float* dst = blockIdx.y ? g_U2 : g_U;
    int r0 = m0 + warp_m + (lane >> 2);
    int cbase = n0 + warp_n + (lane & 3) * 2;
    #pragma unroll
    for (int mt = 0; mt < 4; mt++) {
        #pragma unroll
        for (int nt = 0; nt < 4; nt++) {
            *(float2*)&dst[(size_t)(r0 + mt * 16) * 1024 + cbase + nt * 8] =
                make_float2(acc[mt][nt][0], acc[mt][nt][1]);
            *(float2*)&dst[(size_t)(r0 + mt * 16 + 8) * 1024 + cbase + nt * 8] =
                make_float2(acc[mt][nt][2], acc[mt][nt][3]);
        }
    }
}

// ---------------------------------------------------------------------------
// Kernel 5: pointwise epilogue (f32x2 head + piecewise-linear MLP)
// ---------------------------------------------------------------------------
__global__ __launch_bounds__(256) void epilogue_kernel(
    const float* __restrict__ x, const int* __restrict__ mask,
    const float* __restrict__ bfs, float* __restrict__ out) {
    __shared__ float s_scd[512];
    __shared__ float s_c12[256];
    __shared__ float s_r56[128];
    __shared__ float s_mt[65], s_msa[65], s_msb[65];
    int tid = threadIdx.x;
    for (int i = tid; i < 512; i += 256) s_scd[i] = g_scd[i];
    s_c12[tid] = g_c12[tid];
    if (tid < 128) s_r56[tid] = g_r56[tid];
    if (tid < 65) { s_mt[tid] = g_mt[tid]; s_msa[tid] = g_msa[tid]; s_msb[tid] = g_msb[tid]; }
    __syncthreads();
    float bfs0 = bfs[0];

    int gid = blockIdx.x * 256 + tid;
    int e = gid * 4;
    int b = e >> 16;
    int rem = e & 65535;
    int j = rem >> 6;
    int tt = rem & 63;
    int c = b * 64 + tt;

    float4 xv = *(const float4*)&x[e];
    int4 mv = *(const int4*)&mask[e];
    size_t ubase = (size_t)j * 1024 + c;
    float4 p1 = *(const float4*)&g_U[ubase];
    float4 p2 = *(const float4*)&g_U2[ubase];
    float4 q1 = *(const float4*)&g_U[ubase + 512];
    float4 q2 = *(const float4*)&g_U2[ubase + 512];
    float4 u1v = make_float4(p1.x + p2.x, p1.y + p2.y, p1.z + p2.z, p1.w + p2.w);
    float4 u2v = make_float4(q1.x + q2.x, q1.y + q2.y, q1.z + q2.z, q1.w + q2.w);
    float sj = g_S[j];

    float x1a[4], mfa[4];
    x1a[0] = mv.x ? xv.x : bfs0; mfa[0] = (float)mv.x;
    x1a[1] = mv.y ? xv.y : bfs0; mfa[1] = (float)mv.y;
    x1a[2] = mv.z ? xv.z : bfs0; mfa[2] = (float)mv.z;
    x1a[3] = mv.w ? xv.w : bfs0; mfa[3] = (float)mv.w;

    unsigned long long x1p[2] = { pack2(x1a[0], x1a[1]), pack2(x1a[2], x1a[3]) };
    unsigned long long mfp[2] = { pack2(mfa[0], mfa[1]), pack2(mfa[2], mfa[3]) };
    unsigned long long u1p[2] = { pack2(u1v.x, u1v.y), pack2(u1v.z, u1v.w) };
    unsigned long long u2p[2] = { pack2(u2v.x, u2v.y), pack2(u2v.z, u2v.w) };

    unsigned long long acc2[2] = { 0ULL, 0ULL };
    #pragma unroll 4
    for (int h = 0; h < 64; h++) {
        ulonglong2 r12 = *(const ulonglong2*)&s_scd[h * 8];
        ulonglong2 r34 = *(const ulonglong2*)&s_scd[h * 8 + 4];
        float2 r56v = *(const float2*)&s_r56[h * 2];
        ulonglong2 cc = *(const ulonglong2*)&s_c12[h * 4];
        float base = fmaf(r56v.x, sj, r56v.y);
        unsigned long long base2 = pack2(base, base);
        #pragma unroll
        for (int q = 0; q < 2; q++) {
            unsigned long long v =
                ffma2(r12.x, x1p[q],
                ffma2(r12.y, mfp[q],
                ffma2(r34.x, u1p[q],
                ffma2(r34.y, u2p[q], base2))));
            unsigned long long av = v & 0x7fffffff7fffffffULL;
            acc2[q] = ffma2(cc.x, v, acc2[q]);
            acc2[q] = ffma2(cc.y, av, acc2[q]);
        }
    }

    float accs[4];
    { U64 p; p.u = acc2[0]; accs[0] = p.f.x; accs[1] = p.f.y; }
    { U64 p; p.u = acc2[1]; accs[2] = p.f.x; accs[3] = p.f.y; }

    float res[4];
    #pragma unroll
    for (int q = 0; q < 4; q++) {
        float xs = accs[q];
        int k = 0;
        #pragma unroll
        for (int step = 64; step > 0; step >>= 1) {
            if (k + step <= 64 && s_mt[k + step] <= xs) k += step;
        }
        res[q] = fmaf(s_msa[k], xs, s_msb[k]);
    }
    *(float4*)&out[e] = make_float4(res[0], res[1], res[2], res[3]);
}

// ---------------------------------------------------------------------------
// Launch
// ---------------------------------------------------------------------------
extern "C" void kernel_launch(void* const* d_in, const int* in_sizes, int n_in,
                              void* d_out, int out_size) {
    const float* x      = (const float*)d_in[0];
    const int*   mask   = (const int*)  d_in[1];
    const float* b_fs   = (const float*)d_in[3];
    const float* W_in   = (const float*)d_in[4];
    const float* b_in   = (const float*)d_in[5];
    const float* adj    = (const float*)d_in[6];
    const float* W_gc   = (const float*)d_in[7];
    const float* b_gc   = (const float*)d_in[8];
    const float* W_lo   = (const float*)d_in[9];
    const float* b_lo   = (const float*)d_in[10];
    const float* prelua = (const float*)d_in[11];
    const float* W_ro   = (const float*)d_in[12];
    const float* b_ro   = (const float*)d_in[13];
    const float* W_o1   = (const float*)d_in[14];
    const float* b_o1   = (const float*)d_in[15];
    const float* W_o2   = (const float*)d_in[16];
    const float* b_o2   = (const float*)d_in[17];
    float* out = (float*)d_out;

    coef_kernel<<<1, 64>>>(W_in, b_in, W_gc, b_gc, W_lo, b_lo, W_ro, prelua,
                           W_o1, b_o1, W_o2, b_o2, b_ro);
    colsum_kernel<<<32, 256>>>(adj);
    dim3 ga(32, 32);
    convertA_kernel<<<ga, dim3(32, 8)>>>(adj);
    dim3 gx(16, 8);
    convertX_kernel<<<gx, 256>>>(x, mask, b_fs);
    mma_kernel<<<dim3(64, 2), 256>>>();
    epilogue_kernel<<<ELEMS / 4 / 256, 256>>>(x, mask, b_fs, out);
}

// round 6
// speedup vs baseline: 1.6519x; 1.0292x over previous
#include <cuda_runtime.h>
#include <cuda_bf16.h>
#include <math_constants.h>
#include <cstdint>

// Problem constants
#define BB 8
#define NN 1024
#define TT 64
#define ELEMS (BB*NN*TT)  // 524288

// Scratch (no allocations allowed)
__device__ __nv_bfloat16 g_Ah[1024 * 1024];  // A[m=j][k=i] = adj[i][j], hi part
__device__ __nv_bfloat16 g_Al[1024 * 1024];  // lo part
__device__ __nv_bfloat16 g_Bh[1024 * 1024];  // B[n=c][k=i] = X[i][c], hi part
__device__ __nv_bfloat16 g_Bl[1024 * 1024];  // lo part (x1 half only; mask half exact)
__device__ float g_U[1024 * 1024];           // U[j*1024 + c]
__device__ float g_S[1024];                  // column sums of adj
// Epilogue coefficient tables
__device__ float g_scd[512];         // [h][8] = r1,r1,r2,r2,r3,r3,r4,r4
__device__ float g_c12[256];         // [h][4] = c1,c1,c2,c2
__device__ float g_r56[128];         // [h][2] = r5,r6
__device__ float g_mt[65];           // sorted MLP breakpoints (1-based)
__device__ float g_msa[65];          // piecewise slope table
__device__ float g_msb[65];          // piecewise intercept table

// ---------- helpers ----------
union U64 { unsigned long long u; float2 f; };

__device__ __forceinline__ unsigned long long ffma2(unsigned long long a,
                                                    unsigned long long b,
                                                    unsigned long long c) {
    unsigned long long d;
    asm("fma.rn.f32x2 %0, %1, %2, %3;" : "=l"(d) : "l"(a), "l"(b), "l"(c));
    return d;
}
__device__ __forceinline__ unsigned long long pack2(float x, float y) {
    U64 u; u.f = make_float2(x, y); return u.u;
}
__device__ __forceinline__ uint32_t smem_u32(const void* p) {
    uint32_t a;
    asm("{ .reg .u64 t; cvta.to.shared.u64 t, %1; cvt.u32.u64 %0, t; }" : "=r"(a) : "l"(p));
    return a;
}
__device__ __forceinline__ void cpasync16(uint32_t s, const void* g) {
    asm volatile("cp.async.cg.shared.global [%0], [%1], 16;" :: "r"(s), "l"(g));
}
#define CP_COMMIT() asm volatile("cp.async.commit_group;" ::: "memory")

__device__ __forceinline__ void ldm_x4(uint32_t& r0, uint32_t& r1, uint32_t& r2,
                                       uint32_t& r3, uint32_t a) {
    asm volatile("ldmatrix.sync.aligned.m8n8.x4.shared.b16 {%0,%1,%2,%3}, [%4];"
                 : "=r"(r0), "=r"(r1), "=r"(r2), "=r"(r3) : "r"(a));
}
__device__ __forceinline__ void ldm_x2(uint32_t& r0, uint32_t& r1, uint32_t a) {
    asm volatile("ldmatrix.sync.aligned.m8n8.x2.shared.b16 {%0,%1}, [%2];"
                 : "=r"(r0), "=r"(r1) : "r"(a));
}
__device__ __forceinline__ void mma_bf16(float& c0, float& c1, float& c2, float& c3,
                                         uint32_t a0, uint32_t a1, uint32_t a2, uint32_t a3,
                                         uint32_t b0, uint32_t b1) {
    asm volatile(
        "mma.sync.aligned.m16n8k16.row.col.f32.bf16.bf16.f32 "
        "{%0,%1,%2,%3}, {%4,%5,%6,%7}, {%8,%9}, {%0,%1,%2,%3};"
        : "+f"(c0), "+f"(c1), "+f"(c2), "+f"(c3)
        : "r"(a0), "r"(a1), "r"(a2), "r"(a3), "r"(b0), "r"(b1));
}

// ---------------------------------------------------------------------------
// Kernel 1: fold all linear layers (h == 0 collapse) + build epilogue tables
// ---------------------------------------------------------------------------
__global__ void coef_kernel(const float* __restrict__ Win, const float* __restrict__ bin,
                            const float* __restrict__ Wgc, const float* __restrict__ bgc,
                            const float* __restrict__ Wlo, const float* __restrict__ blo,
                            const float* __restrict__ Wro, const float* __restrict__ prelu_a,
                            const float* __restrict__ Wo1, const float* __restrict__ bo1,
                            const float* __restrict__ Wo2, const float* __restrict__ bo2,
                            const float* __restrict__ bro) {
    __shared__ float sA[64], sC[64], sB[64];
    __shared__ float G[6][64];
    __shared__ float st[64], scz[64];
    __shared__ float srt_t[64], srt_a[64], srt_b[64];
    __shared__ int   srt_p[64];
    int t = threadIdx.x;  // 0..63
    sA[t] = Win[t * 66 + 0];
    sC[t] = Win[t * 66 + 1];
    sB[t] = bin[t];
    __syncthreads();
    float g1 = 0, g2 = 0, g3 = 0, g4 = 0, g5 = 0, g6 = 0;
    for (int h = 0; h < 64; h++) {
        float w0 = Wgc[t * 128 + h];
        float w1 = Wgc[t * 128 + 64 + h];
        g1 = fmaf(w0, sA[h], g1);
        g2 = fmaf(w0, sC[h], g2);
        g3 = fmaf(w0, sB[h], g3);
        g4 = fmaf(w1, sA[h], g4);
        g5 = fmaf(w1, sC[h], g5);
        g6 = fmaf(w1, sB[h], g6);
    }
    G[0][t] = g1; G[1][t] = g2; G[2][t] = g4;
    G[3][t] = g5; G[4][t] = g6; G[5][t] = g3 + bgc[t];
    __syncthreads();
    float r[6] = {0, 0, 0, 0, 0, 0};
    for (int o = 0; o < 64; o++) {
        float w = Wlo[t * 128 + o];
        r[0] = fmaf(w, G[0][o], r[0]);
        r[1] = fmaf(w, G[1][o], r[1]);
        r[2] = fmaf(w, G[2][o], r[2]);
        r[3] = fmaf(w, G[3][o], r[3]);
        r[4] = fmaf(w, G[4][o], r[4]);
        r[5] = fmaf(w, G[5][o], r[5]);
    }
    r[5] += blo[t];
    g_scd[t * 8 + 0] = r[0]; g_scd[t * 8 + 1] = r[0];
    g_scd[t * 8 + 2] = r[1]; g_scd[t * 8 + 3] = r[1];
    g_scd[t * 8 + 4] = r[2]; g_scd[t * 8 + 5] = r[2];
    g_scd[t * 8 + 6] = r[3]; g_scd[t * 8 + 7] = r[3];
    g_r56[t * 2 + 0] = r[4]; g_r56[t * 2 + 1] = r[5];
    float wr = Wro[t];
    float wp = wr;
    float wn = wr * prelu_a[0];
    float c1 = 0.5f * (wp + wn);
    float c2 = 0.5f * (wp - wn);
    g_c12[t * 4 + 0] = c1; g_c12[t * 4 + 1] = c1;
    g_c12[t * 4 + 2] = c2; g_c12[t * 4 + 3] = c2;

    // piecewise-linear MLP tables
    float s1 = Wo1[t];
    float s2p = fmaf(s1, bro[0], bo1[t]);
    float s3 = Wo2[t];
    float tf, af, bf, cz = 0.f;
    int isP;
    if (s1 > 0.f)      { tf = -s2p / s1; isP = 1; af = s3 * s1; bf = s3 * s2p; }
    else if (s1 < 0.f) { tf = -s2p / s1; isP = 0; af = s3 * s1; bf = s3 * s2p; }
    else               { tf = CUDART_INF_F; isP = 0; af = 0.f; bf = 0.f;
                         cz = s3 * fmaxf(s2p, 0.f); }
    st[t] = tf; scz[t] = cz;
    __syncthreads();
    int rank = 0;
    for (int g = 0; g < 64; g++) {
        float tg = st[g];
        if (tg < tf || (tg == tf && g < t)) rank++;
    }
    srt_t[rank] = tf; srt_a[rank] = af; srt_b[rank] = bf; srt_p[rank] = isP;
    __syncthreads();
    float C0 = bo2[0];
    for (int g = 0; g < 64; g++) C0 += scz[g];
    for (int k = t; k <= 64; k += 64) {
        float A = 0.f, Bv = 0.f;
        for (int i = 0; i < 64; i++) {
            bool act = srt_p[i] ? (i < k) : (i >= k);
            if (act) { A += srt_a[i]; Bv += srt_b[i]; }
        }
        g_msa[k] = A;
        g_msb[k] = Bv + C0;
    }
    if (t < 64) g_mt[t + 1] = srt_t[t];
    if (t == 0) g_mt[0] = -CUDART_INF_F;
}

// ---------------------------------------------------------------------------
// Kernel 2: s[j] = sum_n adj[n, j]
// ---------------------------------------------------------------------------
__global__ void colsum_kernel(const float* __restrict__ adj) {
    int lane = threadIdx.x & 31;
    int grp  = threadIdx.x >> 5;
    int j = blockIdx.x * 32 + lane;
    float s = 0.f;
    for (int n = grp; n < 1024; n += 8) s += adj[n * 1024 + j];
    __shared__ float red[8][32];
    red[grp][lane] = s;
    __syncthreads();
    if (grp == 0) {
        float tot = 0.f;
        #pragma unroll
        for (int k = 0; k < 8; k++) tot += red[k][lane];
        g_S[j] = tot;
    }
}

// ---------------------------------------------------------------------------
// Kernel 3a: transpose + split adj -> Ah/Al bf16, layout [m=j][k=i]
// ---------------------------------------------------------------------------
__global__ void convertA_kernel(const float* __restrict__ adj) {
    __shared__ float tile[32][33];
    int tx = threadIdx.x, ty = threadIdx.y;  // 32 x 8
    int j0 = blockIdx.x * 32, i0 = blockIdx.y * 32;
    #pragma unroll
    for (int s = 0; s < 4; s++)
        tile[ty + 8 * s][tx] = adj[(i0 + ty + 8 * s) * 1024 + j0 + tx];
    __syncthreads();
    #pragma unroll
    for (int s = 0; s < 4; s++) {
        float v = tile[tx][ty + 8 * s];
        __nv_bfloat16 h = __float2bfloat16_rn(v);
        __nv_bfloat16 l = __float2bfloat16_rn(v - __bfloat162float(h));
        int idx = (j0 + ty + 8 * s) * 1024 + i0 + tx;
        g_Ah[idx] = h;
        g_Al[idx] = l;
    }
}

// ---------------------------------------------------------------------------
// Kernel 3b: build B[n=c][k=i] bf16 hi/lo from x, mask
// Block: 32 nodes x 64 t for one b. Grid (32, 8) = 256 blocks.
// ---------------------------------------------------------------------------
__global__ __launch_bounds__(256) void convertX_kernel(const float* __restrict__ x,
                                                       const int* __restrict__ mask,
                                                       const float* __restrict__ bfs) {
    __shared__ float sx[32][65];
    __shared__ float sm[32][65];
    int tid = threadIdx.x;
    int b = blockIdx.y, i0 = blockIdx.x * 32;
    // load 32 rows x 64 cols
    int r = tid >> 3;            // 0..31
    int c8 = (tid & 7) * 8;      // 0..56
    int base = (b * 1024 + i0 + r) * 64 + c8;
    {
        float4 v0 = *(const float4*)&x[base];
        float4 v1 = *(const float4*)&x[base + 4];
        int4 m0v = *(const int4*)&mask[base];
        int4 m1v = *(const int4*)&mask[base + 4];
        sx[r][c8 + 0] = v0.x; sx[r][c8 + 1] = v0.y; sx[r][c8 + 2] = v0.z; sx[r][c8 + 3] = v0.w;
        sx[r][c8 + 4] = v1.x; sx[r][c8 + 5] = v1.y; sx[r][c8 + 6] = v1.z; sx[r][c8 + 7] = v1.w;
        sm[r][c8 + 0] = (float)m0v.x; sm[r][c8 + 1] = (float)m0v.y;
        sm[r][c8 + 2] = (float)m0v.z; sm[r][c8 + 3] = (float)m0v.w;
        sm[r][c8 + 4] = (float)m1v.x; sm[r][c8 + 5] = (float)m1v.y;
        sm[r][c8 + 6] = (float)m1v.z; sm[r][c8 + 7] = (float)m1v.w;
    }
    __syncthreads();
    float bfs0 = bfs[0];
    int t = tid >> 2;            // 0..63 (time index)
    int iq = (tid & 3) * 8;      // node sub-block
    __align__(16) __nv_bfloat16 hh[8], ll[8], mh[8];
    #pragma unroll
    for (int q = 0; q < 8; q++) {
        float mv = sm[iq + q][t];
        float xv = sx[iq + q][t];
        float x1 = (mv != 0.0f) ? xv : bfs0;
        __nv_bfloat16 h = __float2bfloat16_rn(x1);
        hh[q] = h;
        ll[q] = __float2bfloat16_rn(x1 - __bfloat162float(h));
        mh[q] = __float2bfloat16_rn(mv);
    }
    int c1 = b * 64 + t;
    int row1 = c1 * 1024 + i0 + iq;
    *(uint4*)&g_Bh[row1] = *(uint4*)&hh[0];
    *(uint4*)&g_Bl[row1] = *(uint4*)&ll[0];
    int row2 = (512 + c1) * 1024 + i0 + iq;
    *(uint4*)&g_Bh[row2] = *(uint4*)&mh[0];
    // g_Bl mask half never read (exact in bf16) -> not written
}

// ---------------------------------------------------------------------------
// Kernel 4: bf16 tensor-core GEMM, paired-N tiles, 2.5-pass split accum.
// CTA tile: M=64 (j) x N=128 paired (cols [n0,n0+64) U [n0+512,n0+576)).
// Passes: p0 Ah*Bh (full), p1 Ah*Bl (x1 half only), p2 Al*Bh (full).
// KC=64, double-buffered cp.async, rows padded to 144B. 128 CTAs.
// ---------------------------------------------------------------------------
#define ROWB 144
#define A_BYTES (64 * ROWB)        // 9216
#define B_OFF   A_BYTES
#define BUFB    (A_BYTES + 128 * ROWB)  // 27648
#define MMA_SMEM (2 * BUFB)        // 55296

__global__ __launch_bounds__(256) void mma_kernel() {
    extern __shared__ __align__(16) char smem[];
    int tid = threadIdx.x;
    int wid = tid >> 5, lane = tid & 31;
    int m0 = (blockIdx.x >> 3) * 64;
    int pn64 = (blockIdx.x & 7) * 64;
    uint32_t sbase = smem_u32(smem);

    // cp.async mappings
    uint32_t soffA[2]; int goffA[2];
    #pragma unroll
    for (int q = 0; q < 2; q++) {
        int c = tid + 256 * q;          // 0..511
        int row = c >> 3, col = c & 7;
        soffA[q] = row * ROWB + col * 16;
        goffA[q] = (m0 + row) * 1024 + col * 8;
    }
    uint32_t soffB[4]; int goffB[4];
    #pragma unroll
    for (int q = 0; q < 4; q++) {
        int c = tid + 256 * q;          // 0..1023
        int row = c >> 3, col = c & 7;
        int gcol = (row < 64) ? (pn64 + row) : (512 + pn64 + row - 64);
        soffB[q] = B_OFF + row * ROWB + col * 16;
        goffB[q] = gcol * 1024 + col * 8;
    }

    const __nv_bfloat16* Apass[3] = {g_Ah, g_Ah, g_Al};
    const __nv_bfloat16* Bpass[3] = {g_Bh, g_Bl, g_Bh};

    float acc[2][4][4];
    #pragma unroll
    for (int mt = 0; mt < 2; mt++)
        #pragma unroll
        for (int nt = 0; nt < 4; nt++)
            #pragma unroll
            for (int q = 0; q < 4; q++) acc[mt][nt][q] = 0.f;

    int warp_m = (wid >> 2) * 32;
    int w2 = wid & 3;                    // 16-col slice within each half
    uint32_t a_off = (warp_m + (lane & 15)) * ROWB + ((lane >> 4) & 1) * 16;
    uint32_t b_off[4];
    #pragma unroll
    for (int nt = 0; nt < 4; nt++) {
        int rowbase = (nt >= 2 ? 64 : 0) + w2 * 16 + (nt & 1) * 8;
        b_off[nt] = B_OFF + (rowbase + (lane & 7)) * ROWB + ((lane >> 3) & 1) * 16;
    }

    // prologue: load iter 0 (pass 0, full) into buf 0
    {
        #pragma unroll
        for (int q = 0; q < 2; q++) cpasync16(sbase + soffA[q], g_Ah + goffA[q]);
        #pragma unroll
        for (int q = 0; q < 4; q++) cpasync16(sbase + soffB[q], g_Bh + goffB[q]);
        CP_COMMIT();
    }

    for (int it = 0; it < 48; it++) {
        int buf = it & 1;
        int p = it >> 4;
        if (it + 1 < 48) {
            int pn = (it + 1) >> 4;
            int k0 = ((it + 1) & 15) * 64;
            const __nv_bfloat16* Aar = Apass[pn];
            const __nv_bfloat16* Bar = Bpass[pn];
            uint32_t sb = sbase + (buf ^ 1) * BUFB;
            #pragma unroll
            for (int q = 0; q < 2; q++) cpasync16(sb + soffA[q], Aar + goffA[q] + k0);
            int nb = (pn == 1) ? 2 : 4;
            for (int q = 0; q < nb; q++) cpasync16(sb + soffB[q], Bar + goffB[q] + k0);
            CP_COMMIT();
            asm volatile("cp.async.wait_group 1;" ::: "memory");
        } else {
            asm volatile("cp.async.wait_group 0;" ::: "memory");
        }
        __syncthreads();

        uint32_t sb = sbase + buf * BUFB;
        int ntmax = (p == 1) ? 2 : 4;
        #pragma unroll
        for (int ks = 0; ks < 4; ks++) {
            uint32_t b0[4], b1[4];
            for (int nt = 0; nt < ntmax; nt++)
                ldm_x2(b0[nt], b1[nt], sb + b_off[nt] + ks * 32);
            uint32_t aaddr = sb + a_off + ks * 32;
            #pragma unroll
            for (int mt = 0; mt < 2; mt++) {
                uint32_t a0, a1, a2, a3;
                ldm_x4(a0, a1, a2, a3, aaddr + mt * 16 * ROWB);
                for (int nt = 0; nt < ntmax; nt++)
                    mma_bf16(acc[mt][nt][0], acc[mt][nt][1], acc[mt][nt][2], acc[mt][nt][3],
                             a0, a1, a2, a3, b0[nt], b1[nt]);
            }
        }
        __syncthreads();
    }

    int r0 = m0 + warp_m + (lane >> 2);
    #pragma unroll
    for (int mt = 0; mt < 2; mt++) {
        #pragma unroll
        for (int nt = 0; nt < 4; nt++) {
            int cb = (nt >= 2 ? 512 : 0) + pn64 + w2 * 16 + (nt & 1) * 8 + (lane & 3) * 2;
            *(float2*)&g_U[(size_t)(r0 + mt * 16) * 1024 + cb] =
                make_float2(acc[mt][nt][0], acc[mt][nt][1]);
            *(float2*)&g_U[(size_t)(r0 + mt * 16 + 8) * 1024 + cb] =
                make_float2(acc[mt][nt][2], acc[mt][nt][3]);
        }
    }
}

// ---------------------------------------------------------------------------
// Kernel 5: pointwise epilogue (f32x2 head + piecewise-linear MLP)
// ---------------------------------------------------------------------------
__global__ __launch_bounds__(256) void epilogue_kernel(
    const float* __restrict__ x, const int* __restrict__ mask,
    const float* __restrict__ bfs, float* __restrict__ out) {
    __shared__ float s_scd[512];
    __shared__ float s_c12[256];
    __shared__ float s_r56[128];
    __shared__ float s_mt[65], s_msa[65], s_msb[65];
    int tid = threadIdx.x;
    for (int i = tid; i < 512; i += 256) s_scd[i] = g_scd[i];
    s_c12[tid] = g_c12[tid];
    if (tid < 128) s_r56[tid] = g_r56[tid];
    if (tid < 65) { s_mt[tid] = g_mt[tid]; s_msa[tid] = g_msa[tid]; s_msb[tid] = g_msb[tid]; }
    __syncthreads();
    float bfs0 = bfs[0];

    int gid = blockIdx.x * 256 + tid;
    int e = gid * 4;
    int b = e >> 16;
    int rem = e & 65535;
    int j = rem >> 6;
    int tt = rem & 63;
    int c = b * 64 + tt;

    float4 xv = *(const float4*)&x[e];
    int4 mv = *(const int4*)&mask[e];
    size_t ubase = (size_t)j * 1024 + c;
    float4 u1v = *(const float4*)&g_U[ubase];
    float4 u2v = *(const float4*)&g_U[ubase + 512];
    float sj = g_S[j];

    float x1a[4], mfa[4];
    x1a[0] = mv.x ? xv.x : bfs0; mfa[0] = (float)mv.x;
    x1a[1] = mv.y ? xv.y : bfs0; mfa[1] = (float)mv.y;
    x1a[2] = mv.z ? xv.z : bfs0; mfa[2] = (float)mv.z;
    x1a[3] = mv.w ? xv.w : bfs0; mfa[3] = (float)mv.w;

    unsigned long long x1p[2] = { pack2(x1a[0], x1a[1]), pack2(x1a[2], x1a[3]) };
    unsigned long long mfp[2] = { pack2(mfa[0], mfa[1]), pack2(mfa[2], mfa[3]) };
    unsigned long long u1p[2] = { pack2(u1v.x, u1v.y), pack2(u1v.z, u1v.w) };
    unsigned long long u2p[2] = { pack2(u2v.x, u2v.y), pack2(u2v.z, u2v.w) };

    unsigned long long acc2[2] = { 0ULL, 0ULL };
    #pragma unroll 4
    for (int h = 0; h < 64; h++) {
        ulonglong2 r12 = *(const ulonglong2*)&s_scd[h * 8];
        ulonglong2 r34 = *(const ulonglong2*)&s_scd[h * 8 + 4];
        float2 r56v = *(const float2*)&s_r56[h * 2];
        ulonglong2 cc = *(const ulonglong2*)&s_c12[h * 4];
        float base = fmaf(r56v.x, sj, r56v.y);
        unsigned long long base2 = pack2(base, base);
        #pragma unroll
        for (int q = 0; q < 2; q++) {
            unsigned long long v =
                ffma2(r12.x, x1p[q],
                ffma2(r12.y, mfp[q],
                ffma2(r34.x, u1p[q],
                ffma2(r34.y, u2p[q], base2))));
            unsigned long long av = v & 0x7fffffff7fffffffULL;
            acc2[q] = ffma2(cc.x, v, acc2[q]);
            acc2[q] = ffma2(cc.y, av, acc2[q]);
        }
    }

    float accs[4];
    { U64 p; p.u = acc2[0]; accs[0] = p.f.x; accs[1] = p.f.y; }
    { U64 p; p.u = acc2[1]; accs[2] = p.f.x; accs[3] = p.f.y; }

    float res[4];
    #pragma unroll
    for (int q = 0; q < 4; q++) {
        float xs = accs[q];
        int k = 0;
        #pragma unroll
        for (int step = 64; step > 0; step >>= 1) {
            if (k + step <= 64 && s_mt[k + step] <= xs) k += step;
        }
        res[q] = fmaf(s_msa[k], xs, s_msb[k]);
    }
    *(float4*)&out[e] = make_float4(res[0], res[1], res[2], res[3]);
}

// ---------------------------------------------------------------------------
// Launch
// ---------------------------------------------------------------------------
extern "C" void kernel_launch(void* const* d_in, const int* in_sizes, int n_in,
                              void* d_out, int out_size) {
    const float* x      = (const float*)d_in[0];
    const int*   mask   = (const int*)  d_in[1];
    const float* b_fs   = (const float*)d_in[3];
    const float* W_in   = (const float*)d_in[4];
    const float* b_in   = (const float*)d_in[5];
    const float* adj    = (const float*)d_in[6];
    const float* W_gc   = (const float*)d_in[7];
    const float* b_gc   = (const float*)d_in[8];
    const float* W_lo   = (const float*)d_in[9];
    const float* b_lo   = (const float*)d_in[10];
    const float* prelua = (const float*)d_in[11];
    const float* W_ro   = (const float*)d_in[12];
    const float* b_ro   = (const float*)d_in[13];
    const float* W_o1   = (const float*)d_in[14];
    const float* b_o1   = (const float*)d_in[15];
    const float* W_o2   = (const float*)d_in[16];
    const float* b_o2   = (const float*)d_in[17];
    float* out = (float*)d_out;

    cudaFuncSetAttribute(mma_kernel, cudaFuncAttributeMaxDynamicSharedMemorySize, MMA_SMEM);

    coef_kernel<<<1, 64>>>(W_in, b_in, W_gc, b_gc, W_lo, b_lo, W_ro, prelua,
                           W_o1, b_o1, W_o2, b_o2, b_ro);
    colsum_kernel<<<32, 256>>>(adj);
    dim3 ga(32, 32);
    convertA_kernel<<<ga, dim3(32, 8)>>>(adj);
    dim3 gx(32, 8);
    convertX_kernel<<<gx, 256>>>(x, mask, b_fs);
    mma_kernel<<<128, 256, MMA_SMEM>>>();
    epilogue_kernel<<<ELEMS / 4 / 256, 256>>>(x, mask, b_fs, out);
}

// round 7
// speedup vs baseline: 1.9058x; 1.1537x over previous
#include <cuda_runtime.h>
#include <cuda_bf16.h>
#include <math_constants.h>
#include <cstdint>

// Problem constants
#define BB 8
#define NN 1024
#define TT 64
#define ELEMS (BB*NN*TT)  // 524288

// Scratch (no allocations allowed)
__device__ __nv_bfloat16 g_Ah[1024 * 1024];  // A[m=j][k=i] = adj[i][j], hi part
__device__ __nv_bfloat16 g_Al[1024 * 1024];  // lo part
__device__ __nv_bfloat16 g_Bh[1024 * 1024];  // B[n=c][k=i] = X[i][c], hi part
__device__ __nv_bfloat16 g_Bl[1024 * 1024];  // lo part (x1 half only; mask half exact)
__device__ float g_U[1024 * 1024];           // U[j*1024 + c]
__device__ float g_S[1024];                  // column sums of adj
// Epilogue coefficient tables
__device__ float g_scd[512];         // [h][8] = r1,r1,r2,r2,r3,r3,r4,r4
__device__ float g_c12[256];         // [h][4] = c1,c1,c2,c2
__device__ float g_r56[128];         // [h][2] = r5,r6
__device__ float g_mt[65];           // sorted MLP breakpoints (1-based)
__device__ float g_msa[65];          // piecewise slope table
__device__ float g_msb[65];          // piecewise intercept table

// ---------- helpers ----------
union U64 { unsigned long long u; float2 f; };

__device__ __forceinline__ unsigned long long ffma2(unsigned long long a,
                                                    unsigned long long b,
                                                    unsigned long long c) {
    unsigned long long d;
    asm("fma.rn.f32x2 %0, %1, %2, %3;" : "=l"(d) : "l"(a), "l"(b), "l"(c));
    return d;
}
__device__ __forceinline__ unsigned long long pack2(float x, float y) {
    U64 u; u.f = make_float2(x, y); return u.u;
}
__device__ __forceinline__ uint32_t smem_u32(const void* p) {
    uint32_t a;
    asm("{ .reg .u64 t; cvta.to.shared.u64 t, %1; cvt.u32.u64 %0, t; }" : "=r"(a) : "l"(p));
    return a;
}
__device__ __forceinline__ void cpasync16(uint32_t s, const void* g) {
    asm volatile("cp.async.cg.shared.global [%0], [%1], 16;" :: "r"(s), "l"(g));
}
#define CP_COMMIT() asm volatile("cp.async.commit_group;" ::: "memory")

__device__ __forceinline__ void ldm_x4(uint32_t& r0, uint32_t& r1, uint32_t& r2,
                                       uint32_t& r3, uint32_t a) {
    asm volatile("ldmatrix.sync.aligned.m8n8.x4.shared.b16 {%0,%1,%2,%3}, [%4];"
                 : "=r"(r0), "=r"(r1), "=r"(r2), "=r"(r3) : "r"(a));
}
__device__ __forceinline__ void ldm_x2(uint32_t& r0, uint32_t& r1, uint32_t a) {
    asm volatile("ldmatrix.sync.aligned.m8n8.x2.shared.b16 {%0,%1}, [%2];"
                 : "=r"(r0), "=r"(r1) : "r"(a));
}
__device__ __forceinline__ void mma_bf16(float& c0, float& c1, float& c2, float& c3,
                                         uint32_t a0, uint32_t a1, uint32_t a2, uint32_t a3,
                                         uint32_t b0, uint32_t b1) {
    asm volatile(
        "mma.sync.aligned.m16n8k16.row.col.f32.bf16.bf16.f32 "
        "{%0,%1,%2,%3}, {%4,%5,%6,%7}, {%8,%9}, {%0,%1,%2,%3};"
        : "+f"(c0), "+f"(c1), "+f"(c2), "+f"(c3)
        : "r"(a0), "r"(a1), "r"(a2), "r"(a3), "r"(b0), "r"(b1));
}

// ---------------------------------------------------------------------------
// Kernel 1: fold all linear layers (h == 0 collapse) + build epilogue tables
// ---------------------------------------------------------------------------
__global__ void coef_kernel(const float* __restrict__ Win, const float* __restrict__ bin,
                            const float* __restrict__ Wgc, const float* __restrict__ bgc,
                            const float* __restrict__ Wlo, const float* __restrict__ blo,
                            const float* __restrict__ Wro, const float* __restrict__ prelu_a,
                            const float* __restrict__ Wo1, const float* __restrict__ bo1,
                            const float* __restrict__ Wo2, const float* __restrict__ bo2,
                            const float* __restrict__ bro) {
    __shared__ float sA[64], sC[64], sB[64];
    __shared__ float G[6][64];
    __shared__ float st[64], scz[64];
    __shared__ float srt_t[64], srt_a[64], srt_b[64];
    __shared__ int   srt_p[64];
    int t = threadIdx.x;  // 0..63
    sA[t] = Win[t * 66 + 0];
    sC[t] = Win[t * 66 + 1];
    sB[t] = bin[t];
    __syncthreads();
    float g1 = 0, g2 = 0, g3 = 0, g4 = 0, g5 = 0, g6 = 0;
    for (int h = 0; h < 64; h++) {
        float w0 = Wgc[t * 128 + h];
        float w1 = Wgc[t * 128 + 64 + h];
        g1 = fmaf(w0, sA[h], g1);
        g2 = fmaf(w0, sC[h], g2);
        g3 = fmaf(w0, sB[h], g3);
        g4 = fmaf(w1, sA[h], g4);
        g5 = fmaf(w1, sC[h], g5);
        g6 = fmaf(w1, sB[h], g6);
    }
    G[0][t] = g1; G[1][t] = g2; G[2][t] = g4;
    G[3][t] = g5; G[4][t] = g6; G[5][t] = g3 + bgc[t];
    __syncthreads();
    float r[6] = {0, 0, 0, 0, 0, 0};
    for (int o = 0; o < 64; o++) {
        float w = Wlo[t * 128 + o];
        r[0] = fmaf(w, G[0][o], r[0]);
        r[1] = fmaf(w, G[1][o], r[1]);
        r[2] = fmaf(w, G[2][o], r[2]);
        r[3] = fmaf(w, G[3][o], r[3]);
        r[4] = fmaf(w, G[4][o], r[4]);
        r[5] = fmaf(w, G[5][o], r[5]);
    }
    r[5] += blo[t];
    g_scd[t * 8 + 0] = r[0]; g_scd[t * 8 + 1] = r[0];
    g_scd[t * 8 + 2] = r[1]; g_scd[t * 8 + 3] = r[1];
    g_scd[t * 8 + 4] = r[2]; g_scd[t * 8 + 5] = r[2];
    g_scd[t * 8 + 6] = r[3]; g_scd[t * 8 + 7] = r[3];
    g_r56[t * 2 + 0] = r[4]; g_r56[t * 2 + 1] = r[5];
    float wr = Wro[t];
    float wp = wr;
    float wn = wr * prelu_a[0];
    float c1 = 0.5f * (wp + wn);
    float c2 = 0.5f * (wp - wn);
    g_c12[t * 4 + 0] = c1; g_c12[t * 4 + 1] = c1;
    g_c12[t * 4 + 2] = c2; g_c12[t * 4 + 3] = c2;

    // piecewise-linear MLP tables
    float s1 = Wo1[t];
    float s2p = fmaf(s1, bro[0], bo1[t]);
    float s3 = Wo2[t];
    float tf, af, bf, cz = 0.f;
    int isP;
    if (s1 > 0.f)      { tf = -s2p / s1; isP = 1; af = s3 * s1; bf = s3 * s2p; }
    else if (s1 < 0.f) { tf = -s2p / s1; isP = 0; af = s3 * s1; bf = s3 * s2p; }
    else               { tf = CUDART_INF_F; isP = 0; af = 0.f; bf = 0.f;
                         cz = s3 * fmaxf(s2p, 0.f); }
    st[t] = tf; scz[t] = cz;
    __syncthreads();
    int rank = 0;
    for (int g = 0; g < 64; g++) {
        float tg = st[g];
        if (tg < tf || (tg == tf && g < t)) rank++;
    }
    srt_t[rank] = tf; srt_a[rank] = af; srt_b[rank] = bf; srt_p[rank] = isP;
    __syncthreads();
    float C0 = bo2[0];
    for (int g = 0; g < 64; g++) C0 += scz[g];
    for (int k = t; k <= 64; k += 64) {
        float A = 0.f, Bv = 0.f;
        for (int i = 0; i < 64; i++) {
            bool act = srt_p[i] ? (i < k) : (i >= k);
            if (act) { A += srt_a[i]; Bv += srt_b[i]; }
        }
        g_msa[k] = A;
        g_msb[k] = Bv + C0;
    }
    if (t < 64) g_mt[t + 1] = srt_t[t];
    if (t == 0) g_mt[0] = -CUDART_INF_F;
}

// ---------------------------------------------------------------------------
// Kernel 2: s[j] = sum_n adj[n, j]
// ---------------------------------------------------------------------------
__global__ void colsum_kernel(const float* __restrict__ adj) {
    int lane = threadIdx.x & 31;
    int grp  = threadIdx.x >> 5;
    int j = blockIdx.x * 32 + lane;
    float s = 0.f;
    for (int n = grp; n < 1024; n += 8) s += adj[n * 1024 + j];
    __shared__ float red[8][32];
    red[grp][lane] = s;
    __syncthreads();
    if (grp == 0) {
        float tot = 0.f;
        #pragma unroll
        for (int k = 0; k < 8; k++) tot += red[k][lane];
        g_S[j] = tot;
    }
}

// ---------------------------------------------------------------------------
// Kernel 3a: transpose + split adj -> Ah/Al bf16, layout [m=j][k=i]
// ---------------------------------------------------------------------------
__global__ void convertA_kernel(const float* __restrict__ adj) {
    __shared__ float tile[32][33];
    int tx = threadIdx.x, ty = threadIdx.y;  // 32 x 8
    int j0 = blockIdx.x * 32, i0 = blockIdx.y * 32;
    #pragma unroll
    for (int s = 0; s < 4; s++)
        tile[ty + 8 * s][tx] = adj[(i0 + ty + 8 * s) * 1024 + j0 + tx];
    __syncthreads();
    #pragma unroll
    for (int s = 0; s < 4; s++) {
        float v = tile[tx][ty + 8 * s];
        __nv_bfloat16 h = __float2bfloat16_rn(v);
        __nv_bfloat16 l = __float2bfloat16_rn(v - __bfloat162float(h));
        int idx = (j0 + ty + 8 * s) * 1024 + i0 + tx;
        g_Ah[idx] = h;
        g_Al[idx] = l;
    }
}

// ---------------------------------------------------------------------------
// Kernel 3b: build B[n=c][k=i] bf16 hi/lo from x, mask
// Block: 32 nodes x 64 t for one b. Grid (32, 8) = 256 blocks.
// ---------------------------------------------------------------------------
__global__ __launch_bounds__(256) void convertX_kernel(const float* __restrict__ x,
                                                       const int* __restrict__ mask,
                                                       const float* __restrict__ bfs) {
    __shared__ float sx[32][65];
    __shared__ float sm[32][65];
    int tid = threadIdx.x;
    int b = blockIdx.y, i0 = blockIdx.x * 32;
    // load 32 rows x 64 cols
    int r = tid >> 3;            // 0..31
    int c8 = (tid & 7) * 8;      // 0..56
    int base = (b * 1024 + i0 + r) * 64 + c8;
    {
        float4 v0 = *(const float4*)&x[base];
        float4 v1 = *(const float4*)&x[base + 4];
        int4 m0v = *(const int4*)&mask[base];
        int4 m1v = *(const int4*)&mask[base + 4];
        sx[r][c8 + 0] = v0.x; sx[r][c8 + 1] = v0.y; sx[r][c8 + 2] = v0.z; sx[r][c8 + 3] = v0.w;
        sx[r][c8 + 4] = v1.x; sx[r][c8 + 5] = v1.y; sx[r][c8 + 6] = v1.z; sx[r][c8 + 7] = v1.w;
        sm[r][c8 + 0] = (float)m0v.x; sm[r][c8 + 1] = (float)m0v.y;
        sm[r][c8 + 2] = (float)m0v.z; sm[r][c8 + 3] = (float)m0v.w;
        sm[r][c8 + 4] = (float)m1v.x; sm[r][c8 + 5] = (float)m1v.y;
        sm[r][c8 + 6] = (float)m1v.z; sm[r][c8 + 7] = (float)m1v.w;
    }
    __syncthreads();
    float bfs0 = bfs[0];
    int t = tid >> 2;            // 0..63 (time index)
    int iq = (tid & 3) * 8;      // node sub-block
    __align__(16) __nv_bfloat16 hh[8], ll[8], mh[8];
    #pragma unroll
    for (int q = 0; q < 8; q++) {
        float mv = sm[iq + q][t];
        float xv = sx[iq + q][t];
        float x1 = (mv != 0.0f) ? xv : bfs0;
        __nv_bfloat16 h = __float2bfloat16_rn(x1);
        hh[q] = h;
        ll[q] = __float2bfloat16_rn(x1 - __bfloat162float(h));
        mh[q] = __float2bfloat16_rn(mv);
    }
    int c1 = b * 64 + t;
    int row1 = c1 * 1024 + i0 + iq;
    *(uint4*)&g_Bh[row1] = *(uint4*)&hh[0];
    *(uint4*)&g_Bl[row1] = *(uint4*)&ll[0];
    int row2 = (512 + c1) * 1024 + i0 + iq;
    *(uint4*)&g_Bh[row2] = *(uint4*)&mh[0];
    // g_Bl mask half never read (exact in bf16) -> not written
}

// ---------------------------------------------------------------------------
// Kernel 4: bf16 tensor-core GEMM, FUSED 3-term accumulation per k-chunk.
// U[j,c] = sum_k (Ah·Bh + Ah·Bl + Al·Bh)(k).
// CTA tile: M=64 x N=128 paired (cols [n0,n0+64) U [n0+512,n0+576)).
// Per k-chunk (KC=64) load Ah, Al, Bh(128 rows), Bl(64 x1 rows) together;
// Bh frags reused by p0+p2, Ah frags by p0+p1 -> 10 LDSM : 20 HMMA per ks.
// 16 iterations, double-buffered cp.async. 128 CTAs, 256 threads.
// ---------------------------------------------------------------------------
#define ROWB 144
#define AH_OFF 0
#define AL_OFF (64 * ROWB)         // 9216
#define BH_OFF (128 * ROWB)        // 18432
#define BL_OFF (256 * ROWB)        // 36864
#define BUFB   (320 * ROWB)        // 46080
#define MMA_SMEM (2 * BUFB)        // 92160

__global__ __launch_bounds__(256) void mma_kernel() {
    extern __shared__ __align__(16) char smem[];
    int tid = threadIdx.x;
    int wid = tid >> 5, lane = tid & 31;
    int m0 = (blockIdx.x >> 3) * 64;
    int pn64 = (blockIdx.x & 7) * 64;
    uint32_t sbase = smem_u32(smem);

    // cp.async mapping: 10 chunks of 16B per thread per iteration (320 rows x 8)
    uint32_t soff[10];
    const __nv_bfloat16* gp[10];
    #pragma unroll
    for (int q = 0; q < 10; q++) {
        int c = tid + 256 * q;          // 0..2559
        int row = c >> 3, col = c & 7;
        soff[q] = row * ROWB + col * 16;
        if (row < 64) {
            gp[q] = g_Ah + (m0 + row) * 1024 + col * 8;
        } else if (row < 128) {
            gp[q] = g_Al + (m0 + row - 64) * 1024 + col * 8;
        } else if (row < 256) {
            int r = row - 128;
            int gcol = (r < 64) ? (pn64 + r) : (512 + pn64 + r - 64);
            gp[q] = g_Bh + gcol * 1024 + col * 8;
        } else {
            gp[q] = g_Bl + (pn64 + row - 256) * 1024 + col * 8;
        }
    }

    float acc[2][4][4];
    #pragma unroll
    for (int mt = 0; mt < 2; mt++)
        #pragma unroll
        for (int nt = 0; nt < 4; nt++)
            #pragma unroll
            for (int q = 0; q < 4; q++) acc[mt][nt][q] = 0.f;

    int warp_m = (wid >> 2) * 32;
    int w2 = wid & 3;                    // 16-col slice within each half
    uint32_t a_rel = (warp_m + (lane & 15)) * ROWB + ((lane >> 4) & 1) * 16;
    uint32_t bh_off[4], bl_off[2];
    #pragma unroll
    for (int nt = 0; nt < 4; nt++) {
        int rowbase = (nt >= 2 ? 64 : 0) + w2 * 16 + (nt & 1) * 8;
        bh_off[nt] = BH_OFF + (rowbase + (lane & 7)) * ROWB + ((lane >> 3) & 1) * 16;
    }
    #pragma unroll
    for (int nt = 0; nt < 2; nt++) {
        int rowbase = w2 * 16 + nt * 8;
        bl_off[nt] = BL_OFF + (rowbase + (lane & 7)) * ROWB + ((lane >> 3) & 1) * 16;
    }

    // prologue: load k-chunk 0 into buf 0
    #pragma unroll
    for (int q = 0; q < 10; q++) cpasync16(sbase + soff[q], gp[q]);
    CP_COMMIT();

    for (int it = 0; it < 16; it++) {
        int buf = it & 1;
        if (it + 1 < 16) {
            int k0 = (it + 1) * 64;
            uint32_t sb = sbase + (buf ^ 1) * BUFB;
            #pragma unroll
            for (int q = 0; q < 10; q++) cpasync16(sb + soff[q], gp[q] + k0);
            CP_COMMIT();
            asm volatile("cp.async.wait_group 1;" ::: "memory");
        } else {
            asm volatile("cp.async.wait_group 0;" ::: "memory");
        }
        __syncthreads();

        uint32_t sb = sbase + buf * BUFB;
        #pragma unroll
        for (int ks = 0; ks < 4; ks++) {
            uint32_t bh0[4], bh1[4], bl0[2], bl1[2];
            uint32_t ah[2][4], al[2][4];
            #pragma unroll
            for (int nt = 0; nt < 4; nt++)
                ldm_x2(bh0[nt], bh1[nt], sb + bh_off[nt] + ks * 32);
            #pragma unroll
            for (int nt = 0; nt < 2; nt++)
                ldm_x2(bl0[nt], bl1[nt], sb + bl_off[nt] + ks * 32);
            #pragma unroll
            for (int mt = 0; mt < 2; mt++)
                ldm_x4(ah[mt][0], ah[mt][1], ah[mt][2], ah[mt][3],
                       sb + AH_OFF + a_rel + mt * 16 * ROWB + ks * 32);
            #pragma unroll
            for (int mt = 0; mt < 2; mt++)
                ldm_x4(al[mt][0], al[mt][1], al[mt][2], al[mt][3],
                       sb + AL_OFF + a_rel + mt * 16 * ROWB + ks * 32);
            // p0: Ah * Bh (all columns)
            #pragma unroll
            for (int mt = 0; mt < 2; mt++)
                #pragma unroll
                for (int nt = 0; nt < 4; nt++)
                    mma_bf16(acc[mt][nt][0], acc[mt][nt][1], acc[mt][nt][2], acc[mt][nt][3],
                             ah[mt][0], ah[mt][1], ah[mt][2], ah[mt][3], bh0[nt], bh1[nt]);
            // p1: Ah * Bl (x1 columns only: nt 0,1)
            #pragma unroll
            for (int mt = 0; mt < 2; mt++)
                #pragma unroll
                for (int nt = 0; nt < 2; nt++)
                    mma_bf16(acc[mt][nt][0], acc[mt][nt][1], acc[mt][nt][2], acc[mt][nt][3],
                             ah[mt][0], ah[mt][1], ah[mt][2], ah[mt][3], bl0[nt], bl1[nt]);
            // p2: Al * Bh (all columns)
            #pragma unroll
            for (int mt = 0; mt < 2; mt++)
                #pragma unroll
                for (int nt = 0; nt < 4; nt++)
                    mma_bf16(acc[mt][nt][0], acc[mt][nt][1], acc[mt][nt][2], acc[mt][nt][3],
                             al[mt][0], al[mt][1], al[mt][2], al[mt][3], bh0[nt], bh1[nt]);
        }
        __syncthreads();
    }

    int r0 = m0 + warp_m + (lane >> 2);
    #pragma unroll
    for (int mt = 0; mt < 2; mt++) {
        #pragma unroll
        for (int nt = 0; nt < 4; nt++) {
            int cb = (nt >= 2 ? 512 : 0) + pn64 + w2 * 16 + (nt & 1) * 8 + (lane & 3) * 2;
            *(float2*)&g_U[(size_t)(r0 + mt * 16) * 1024 + cb] =
                make_float2(acc[mt][nt][0], acc[mt][nt][1]);
            *(float2*)&g_U[(size_t)(r0 + mt * 16 + 8) * 1024 + cb] =
                make_float2(acc[mt][nt][2], acc[mt][nt][3]);
        }
    }
}

// ---------------------------------------------------------------------------
// Kernel 5: pointwise epilogue (f32x2 head + piecewise-linear MLP)
// ---------------------------------------------------------------------------
__global__ __launch_bounds__(256) void epilogue_kernel(
    const float* __restrict__ x, const int* __restrict__ mask,
    const float* __restrict__ bfs, float* __restrict__ out) {
    __shared__ float s_scd[512];
    __shared__ float s_c12[256];
    __shared__ float s_r56[128];
    __shared__ float s_mt[65], s_msa[65], s_msb[65];
    int tid = threadIdx.x;
    for (int i = tid; i < 512; i += 256) s_scd[i] = g_scd[i];
    s_c12[tid] = g_c12[tid];
    if (tid < 128) s_r56[tid] = g_r56[tid];
    if (tid < 65) { s_mt[tid] = g_mt[tid]; s_msa[tid] = g_msa[tid]; s_msb[tid] = g_msb[tid]; }
    __syncthreads();
    float bfs0 = bfs[0];

    int gid = blockIdx.x * 256 + tid;
    int e = gid * 4;
    int b = e >> 16;
    int rem = e & 65535;
    int j = rem >> 6;
    int tt = rem & 63;
    int c = b * 64 + tt;

    float4 xv = *(const float4*)&x[e];
    int4 mv = *(const int4*)&mask[e];
    size_t ubase = (size_t)j * 1024 + c;
    float4 u1v = *(const float4*)&g_U[ubase];
    float4 u2v = *(const float4*)&g_U[ubase + 512];
    float sj = g_S[j];

    float x1a[4], mfa[4];
    x1a[0] = mv.x ? xv.x : bfs0; mfa[0] = (float)mv.x;
    x1a[1] = mv.y ? xv.y : bfs0; mfa[1] = (float)mv.y;
    x1a[2] = mv.z ? xv.z : bfs0; mfa[2] = (float)mv.z;
    x1a[3] = mv.w ? xv.w : bfs0; mfa[3] = (float)mv.w;

    unsigned long long x1p[2] = { pack2(x1a[0], x1a[1]), pack2(x1a[2], x1a[3]) };
    unsigned long long mfp[2] = { pack2(mfa[0], mfa[1]), pack2(mfa[2], mfa[3]) };
    unsigned long long u1p[2] = { pack2(u1v.x, u1v.y), pack2(u1v.z, u1v.w) };
    unsigned long long u2p[2] = { pack2(u2v.x, u2v.y), pack2(u2v.z, u2v.w) };

    unsigned long long acc2[2] = { 0ULL, 0ULL };
    #pragma unroll 4
    for (int h = 0; h < 64; h++) {
        ulonglong2 r12 = *(const ulonglong2*)&s_scd[h * 8];
        ulonglong2 r34 = *(const ulonglong2*)&s_scd[h * 8 + 4];
        float2 r56v = *(const float2*)&s_r56[h * 2];
        ulonglong2 cc = *(const ulonglong2*)&s_c12[h * 4];
        float base = fmaf(r56v.x, sj, r56v.y);
        unsigned long long base2 = pack2(base, base);
        #pragma unroll
        for (int q = 0; q < 2; q++) {
            unsigned long long v =
                ffma2(r12.x, x1p[q],
                ffma2(r12.y, mfp[q],
                ffma2(r34.x, u1p[q],
                ffma2(r34.y, u2p[q], base2))));
            unsigned long long av = v & 0x7fffffff7fffffffULL;
            acc2[q] = ffma2(cc.x, v, acc2[q]);
            acc2[q] = ffma2(cc.y, av, acc2[q]);
        }
    }

    float accs[4];
    { U64 p; p.u = acc2[0]; accs[0] = p.f.x; accs[1] = p.f.y; }
    { U64 p; p.u = acc2[1]; accs[2] = p.f.x; accs[3] = p.f.y; }

    float res[4];
    #pragma unroll
    for (int q = 0; q < 4; q++) {
        float xs = accs[q];
        int k = 0;
        #pragma unroll
        for (int step = 64; step > 0; step >>= 1) {
            if (k + step <= 64 && s_mt[k + step] <= xs) k += step;
        }
        res[q] = fmaf(s_msa[k], xs, s_msb[k]);
    }
    *(float4*)&out[e] = make_float4(res[0], res[1], res[2], res[3]);
}

// ---------------------------------------------------------------------------
// Launch
// ---------------------------------------------------------------------------
extern "C" void kernel_launch(void* const* d_in, const int* in_sizes, int n_in,
                              void* d_out, int out_size) {
    const float* x      = (const float*)d_in[0];
    const int*   mask   = (const int*)  d_in[1];
    const float* b_fs   = (const float*)d_in[3];
    const float* W_in   = (const float*)d_in[4];
    const float* b_in   = (const float*)d_in[5];
    const float* adj    = (const float*)d_in[6];
    const float* W_gc   = (const float*)d_in[7];
    const float* b_gc   = (const float*)d_in[8];
    const float* W_lo   = (const float*)d_in[9];
    const float* b_lo   = (const float*)d_in[10];
    const float* prelua = (const float*)d_in[11];
    const float* W_ro   = (const float*)d_in[12];
    const float* b_ro   = (const float*)d_in[13];
    const float* W_o1   = (const float*)d_in[14];
    const float* b_o1   = (const float*)d_in[15];
    const float* W_o2   = (const float*)d_in[16];
    const float* b_o2   = (const float*)d_in[17];
    float* out = (float*)d_out;

    cudaFuncSetAttribute(mma_kernel, cudaFuncAttributeMaxDynamicSharedMemorySize, MMA_SMEM);

    coef_kernel<<<1, 64>>>(W_in, b_in, W_gc, b_gc, W_lo, b_lo, W_ro, prelua,
                           W_o1, b_o1, W_o2, b_o2, b_ro);
    colsum_kernel<<<32, 256>>>(adj);
    dim3 ga(32, 32);
    convertA_kernel<<<ga, dim3(32, 8)>>>(adj);
    dim3 gx(32, 8);
    convertX_kernel<<<gx, 256>>>(x, mask, b_fs);
    mma_kernel<<<128, 256, MMA_SMEM>>>();
    epilogue_kernel<<<ELEMS / 4 / 256, 256>>>(x, mask, b_fs, out);
}

// round 8
// speedup vs baseline: 2.0961x; 1.0998x over previous
#include <cuda_runtime.h>
#include <cuda_bf16.h>
#include <math_constants.h>
#include <cstdint>

// Problem constants
#define BB 8
#define NN 1024
#define TT 64
#define ELEMS (BB*NN*TT)  // 524288

// Scratch (no allocations allowed)
__device__ __nv_bfloat16 g_Ah[1024 * 1024];  // A[m=j][k=i] = adj[i][j], hi part
__device__ __nv_bfloat16 g_Al[1024 * 1024];  // lo part
__device__ __nv_bfloat16 g_Bh[1024 * 1024];  // B[n=c][k=i] = X[i][c], hi part
__device__ __nv_bfloat16 g_Bl[1024 * 1024];  // lo part (x1 half only; mask half exact)
__device__ float g_U[1024 * 1024];           // U[j*1024 + c]
__device__ float g_S[1024];                  // column sums of adj (atomic-accumulated)
// Epilogue coefficient tables
__device__ float g_scd[512];         // [h][8] = r1,r1,r2,r2,r3,r3,r4,r4
__device__ float g_c12[256];         // [h][4] = c1,c1,c2,c2
__device__ float g_r56[128];         // [h][2] = r5,r6
__device__ float g_mt[65];           // sorted MLP breakpoints (1-based)
__device__ float g_msa[65];          // piecewise slope table
__device__ float g_msb[65];          // piecewise intercept table

// ---------- helpers ----------
union U64 { unsigned long long u; float2 f; };

__device__ __forceinline__ unsigned long long ffma2(unsigned long long a,
                                                    unsigned long long b,
                                                    unsigned long long c) {
    unsigned long long d;
    asm("fma.rn.f32x2 %0, %1, %2, %3;" : "=l"(d) : "l"(a), "l"(b), "l"(c));
    return d;
}
__device__ __forceinline__ unsigned long long pack2(float x, float y) {
    U64 u; u.f = make_float2(x, y); return u.u;
}
__device__ __forceinline__ uint32_t smem_u32(const void* p) {
    uint32_t a;
    asm("{ .reg .u64 t; cvta.to.shared.u64 t, %1; cvt.u32.u64 %0, t; }" : "=r"(a) : "l"(p));
    return a;
}
__device__ __forceinline__ void cpasync16(uint32_t s, const void* g) {
    asm volatile("cp.async.cg.shared.global [%0], [%1], 16;" :: "r"(s), "l"(g));
}
#define CP_COMMIT() asm volatile("cp.async.commit_group;" ::: "memory")

__device__ __forceinline__ void ldm_x4(uint32_t& r0, uint32_t& r1, uint32_t& r2,
                                       uint32_t& r3, uint32_t a) {
    asm volatile("ldmatrix.sync.aligned.m8n8.x4.shared.b16 {%0,%1,%2,%3}, [%4];"
                 : "=r"(r0), "=r"(r1), "=r"(r2), "=r"(r3) : "r"(a));
}
__device__ __forceinline__ void mma_bf16(float& c0, float& c1, float& c2, float& c3,
                                         uint32_t a0, uint32_t a1, uint32_t a2, uint32_t a3,
                                         uint32_t b0, uint32_t b1) {
    asm volatile(
        "mma.sync.aligned.m16n8k16.row.col.f32.bf16.bf16.f32 "
        "{%0,%1,%2,%3}, {%4,%5,%6,%7}, {%8,%9}, {%0,%1,%2,%3};"
        : "+f"(c0), "+f"(c1), "+f"(c2), "+f"(c3)
        : "r"(a0), "r"(a1), "r"(a2), "r"(a3), "r"(b0), "r"(b1));
}

// ---------------------------------------------------------------------------
// Kernel 1: fold all linear layers (h == 0 collapse) + build epilogue tables
// Also zeroes g_S for the fused colsum atomics (stream-ordered before convertA).
// ---------------------------------------------------------------------------
__global__ void coef_kernel(const float* __restrict__ Win, const float* __restrict__ bin,
                            const float* __restrict__ Wgc, const float* __restrict__ bgc,
                            const float* __restrict__ Wlo, const float* __restrict__ blo,
                            const float* __restrict__ Wro, const float* __restrict__ prelu_a,
                            const float* __restrict__ Wo1, const float* __restrict__ bo1,
                            const float* __restrict__ Wo2, const float* __restrict__ bo2,
                            const float* __restrict__ bro) {
    __shared__ float sA[64], sC[64], sB[64];
    __shared__ float G[6][64];
    __shared__ float st[64], scz[64];
    __shared__ float srt_t[64], srt_a[64], srt_b[64];
    __shared__ int   srt_p[64];
    int t = threadIdx.x;  // 0..63
    for (int i = t; i < 1024; i += 64) g_S[i] = 0.f;
    sA[t] = Win[t * 66 + 0];
    sC[t] = Win[t * 66 + 1];
    sB[t] = bin[t];
    __syncthreads();
    float g1 = 0, g2 = 0, g3 = 0, g4 = 0, g5 = 0, g6 = 0;
    for (int h = 0; h < 64; h++) {
        float w0 = Wgc[t * 128 + h];
        float w1 = Wgc[t * 128 + 64 + h];
        g1 = fmaf(w0, sA[h], g1);
        g2 = fmaf(w0, sC[h], g2);
        g3 = fmaf(w0, sB[h], g3);
        g4 = fmaf(w1, sA[h], g4);
        g5 = fmaf(w1, sC[h], g5);
        g6 = fmaf(w1, sB[h], g6);
    }
    G[0][t] = g1; G[1][t] = g2; G[2][t] = g4;
    G[3][t] = g5; G[4][t] = g6; G[5][t] = g3 + bgc[t];
    __syncthreads();
    float r[6] = {0, 0, 0, 0, 0, 0};
    for (int o = 0; o < 64; o++) {
        float w = Wlo[t * 128 + o];
        r[0] = fmaf(w, G[0][o], r[0]);
        r[1] = fmaf(w, G[1][o], r[1]);
        r[2] = fmaf(w, G[2][o], r[2]);
        r[3] = fmaf(w, G[3][o], r[3]);
        r[4] = fmaf(w, G[4][o], r[4]);
        r[5] = fmaf(w, G[5][o], r[5]);
    }
    r[5] += blo[t];
    g_scd[t * 8 + 0] = r[0]; g_scd[t * 8 + 1] = r[0];
    g_scd[t * 8 + 2] = r[1]; g_scd[t * 8 + 3] = r[1];
    g_scd[t * 8 + 4] = r[2]; g_scd[t * 8 + 5] = r[2];
    g_scd[t * 8 + 6] = r[3]; g_scd[t * 8 + 7] = r[3];
    g_r56[t * 2 + 0] = r[4]; g_r56[t * 2 + 1] = r[5];
    float wr = Wro[t];
    float wp = wr;
    float wn = wr * prelu_a[0];
    float c1 = 0.5f * (wp + wn);
    float c2 = 0.5f * (wp - wn);
    g_c12[t * 4 + 0] = c1; g_c12[t * 4 + 1] = c1;
    g_c12[t * 4 + 2] = c2; g_c12[t * 4 + 3] = c2;

    // piecewise-linear MLP tables
    float s1 = Wo1[t];
    float s2p = fmaf(s1, bro[0], bo1[t]);
    float s3 = Wo2[t];
    float tf, af, bf, cz = 0.f;
    int isP;
    if (s1 > 0.f)      { tf = -s2p / s1; isP = 1; af = s3 * s1; bf = s3 * s2p; }
    else if (s1 < 0.f) { tf = -s2p / s1; isP = 0; af = s3 * s1; bf = s3 * s2p; }
    else               { tf = CUDART_INF_F; isP = 0; af = 0.f; bf = 0.f;
                         cz = s3 * fmaxf(s2p, 0.f); }
    st[t] = tf; scz[t] = cz;
    __syncthreads();
    int rank = 0;
    for (int g = 0; g < 64; g++) {
        float tg = st[g];
        if (tg < tf || (tg == tf && g < t)) rank++;
    }
    srt_t[rank] = tf; srt_a[rank] = af; srt_b[rank] = bf; srt_p[rank] = isP;
    __syncthreads();
    float C0 = bo2[0];
    for (int g = 0; g < 64; g++) C0 += scz[g];
    for (int k = t; k <= 64; k += 64) {
        float A = 0.f, Bv = 0.f;
        for (int i = 0; i < 64; i++) {
            bool act = srt_p[i] ? (i < k) : (i >= k);
            if (act) { A += srt_a[i]; Bv += srt_b[i]; }
        }
        g_msa[k] = A;
        g_msb[k] = Bv + C0;
    }
    if (t < 64) g_mt[t + 1] = srt_t[t];
    if (t == 0) g_mt[0] = -CUDART_INF_F;
}

// ---------------------------------------------------------------------------
// Kernel 3a: transpose + split adj -> Ah/Al bf16 + fused column-sum atomics
// ---------------------------------------------------------------------------
__global__ void convertA_kernel(const float* __restrict__ adj) {
    __shared__ float tile[32][33];
    int tx = threadIdx.x, ty = threadIdx.y;  // 32 x 8
    int j0 = blockIdx.x * 32, i0 = blockIdx.y * 32;
    #pragma unroll
    for (int s = 0; s < 4; s++)
        tile[ty + 8 * s][tx] = adj[(i0 + ty + 8 * s) * 1024 + j0 + tx];
    __syncthreads();
    #pragma unroll
    for (int s = 0; s < 4; s++) {
        float v = tile[tx][ty + 8 * s];
        __nv_bfloat16 h = __float2bfloat16_rn(v);
        __nv_bfloat16 l = __float2bfloat16_rn(v - __bfloat162float(h));
        int idx = (j0 + ty + 8 * s) * 1024 + i0 + tx;
        g_Ah[idx] = h;
        g_Al[idx] = l;
    }
    // fused colsum: s[j0+tx] += sum_r tile[r][tx]  (conflict-free: stride-33 rows)
    if (ty == 0) {
        float s = 0.f;
        #pragma unroll
        for (int r = 0; r < 32; r++) s += tile[r][tx];
        atomicAdd(&g_S[j0 + tx], s);
    }
}

// ---------------------------------------------------------------------------
// Kernel 3b: build B[n=c][k=i] bf16 hi/lo from x, mask
// Block: 32 nodes x 64 t for one b. Grid (32, 8) = 256 blocks.
// ---------------------------------------------------------------------------
__global__ __launch_bounds__(256) void convertX_kernel(const float* __restrict__ x,
                                                       const int* __restrict__ mask,
                                                       const float* __restrict__ bfs) {
    __shared__ float sx[32][65];
    __shared__ float sm[32][65];
    int tid = threadIdx.x;
    int b = blockIdx.y, i0 = blockIdx.x * 32;
    int r = tid >> 3;            // 0..31
    int c8 = (tid & 7) * 8;      // 0..56
    int base = (b * 1024 + i0 + r) * 64 + c8;
    {
        float4 v0 = *(const float4*)&x[base];
        float4 v1 = *(const float4*)&x[base + 4];
        int4 m0v = *(const int4*)&mask[base];
        int4 m1v = *(const int4*)&mask[base + 4];
        sx[r][c8 + 0] = v0.x; sx[r][c8 + 1] = v0.y; sx[r][c8 + 2] = v0.z; sx[r][c8 + 3] = v0.w;
        sx[r][c8 + 4] = v1.x; sx[r][c8 + 5] = v1.y; sx[r][c8 + 6] = v1.z; sx[r][c8 + 7] = v1.w;
        sm[r][c8 + 0] = (float)m0v.x; sm[r][c8 + 1] = (float)m0v.y;
        sm[r][c8 + 2] = (float)m0v.z; sm[r][c8 + 3] = (float)m0v.w;
        sm[r][c8 + 4] = (float)m1v.x; sm[r][c8 + 5] = (float)m1v.y;
        sm[r][c8 + 6] = (float)m1v.z; sm[r][c8 + 7] = (float)m1v.w;
    }
    __syncthreads();
    float bfs0 = bfs[0];
    int t = tid >> 2;            // 0..63 (time index)
    int iq = (tid & 3) * 8;      // node sub-block
    __align__(16) __nv_bfloat16 hh[8], ll[8], mh[8];
    #pragma unroll
    for (int q = 0; q < 8; q++) {
        float mv = sm[iq + q][t];
        float xv = sx[iq + q][t];
        float x1 = (mv != 0.0f) ? xv : bfs0;
        __nv_bfloat16 h = __float2bfloat16_rn(x1);
        hh[q] = h;
        ll[q] = __float2bfloat16_rn(x1 - __bfloat162float(h));
        mh[q] = __float2bfloat16_rn(mv);
    }
    int c1 = b * 64 + t;
    int row1 = c1 * 1024 + i0 + iq;
    *(uint4*)&g_Bh[row1] = *(uint4*)&hh[0];
    *(uint4*)&g_Bl[row1] = *(uint4*)&ll[0];
    int row2 = (512 + c1) * 1024 + i0 + iq;
    *(uint4*)&g_Bh[row2] = *(uint4*)&mh[0];
}

// ---------------------------------------------------------------------------
// Kernel 4: bf16 tensor-core GEMM, fused 3-term accumulation per k-chunk.
// 3-stage cp.async pipeline, x4-ldmatrix for B, ks-level frag pipelining.
// CTA tile M=64 x N=128 paired. 128 CTAs, 256 threads, 16 k-iterations.
// ---------------------------------------------------------------------------
#define ROWB 144
#define AH_OFF 0
#define AL_OFF (64 * ROWB)         // 9216
#define BH_OFF (128 * ROWB)        // 18432
#define BL_OFF (256 * ROWB)        // 36864
#define BUFB   (320 * ROWB)        // 46080
#define MMA_SMEM (3 * BUFB)        // 138240

struct Frags {
    uint32_t ah[2][4], al[2][4];
    uint32_t bh0[4], bh1[4], bl0[2], bl1[2];
};

__device__ __forceinline__ void load_frags(Frags& f, uint32_t sb, int ks,
                                           uint32_t a_rel, uint32_t bh_b0,
                                           uint32_t bh_b1, uint32_t bl_b) {
    uint32_t o = ks * 32;
    ldm_x4(f.bh0[0], f.bh1[0], f.bh0[1], f.bh1[1], sb + bh_b0 + o);
    ldm_x4(f.bh0[2], f.bh1[2], f.bh0[3], f.bh1[3], sb + bh_b1 + o);
    ldm_x4(f.bl0[0], f.bl1[0], f.bl0[1], f.bl1[1], sb + bl_b + o);
    ldm_x4(f.ah[0][0], f.ah[0][1], f.ah[0][2], f.ah[0][3], sb + AH_OFF + a_rel + o);
    ldm_x4(f.ah[1][0], f.ah[1][1], f.ah[1][2], f.ah[1][3], sb + AH_OFF + a_rel + 16 * ROWB + o);
    ldm_x4(f.al[0][0], f.al[0][1], f.al[0][2], f.al[0][3], sb + AL_OFF + a_rel + o);
    ldm_x4(f.al[1][0], f.al[1][1], f.al[1][2], f.al[1][3], sb + AL_OFF + a_rel + 16 * ROWB + o);
}

__global__ __launch_bounds__(256) void mma_kernel() {
    extern __shared__ __align__(16) char smem[];
    int tid = threadIdx.x;
    int wid = tid >> 5, lane = tid & 31;
    int m0 = (blockIdx.x >> 3) * 64;
    int pn64 = (blockIdx.x & 7) * 64;
    uint32_t sbase = smem_u32(smem);

    // cp.async mapping: 10 chunks of 16B per thread per iteration (320 rows x 8)
    uint32_t soff[10];
    const __nv_bfloat16* gp[10];
    #pragma unroll
    for (int q = 0; q < 10; q++) {
        int c = tid + 256 * q;          // 0..2559
        int row = c >> 3, col = c & 7;
        soff[q] = row * ROWB + col * 16;
        if (row < 64) {
            gp[q] = g_Ah + (m0 + row) * 1024 + col * 8;
        } else if (row < 128) {
            gp[q] = g_Al + (m0 + row - 64) * 1024 + col * 8;
        } else if (row < 256) {
            int r = row - 128;
            int gcol = (r < 64) ? (pn64 + r) : (512 + pn64 + r - 64);
            gp[q] = g_Bh + gcol * 1024 + col * 8;
        } else {
            gp[q] = g_Bl + (pn64 + row - 256) * 1024 + col * 8;
        }
    }

    float acc[2][4][4];
    #pragma unroll
    for (int mt = 0; mt < 2; mt++)
        #pragma unroll
        for (int nt = 0; nt < 4; nt++)
            #pragma unroll
            for (int q = 0; q < 4; q++) acc[mt][nt][q] = 0.f;

    int warp_m = (wid >> 2) * 32;
    int w2 = wid & 3;                    // 16-col slice within each half
    uint32_t a_rel = (warp_m + (lane & 15)) * ROWB + ((lane >> 4) & 1) * 16;
    // x4 B addressing: lanes 0-7 m0(n 0-7,k0-7), 8-15 m1(k8-15), 16-23 m2(n 8-15), 24-31 m3
    uint32_t x4row = (lane & 7) + ((lane >> 4) & 1) * 8;
    uint32_t x4chk = ((lane >> 3) & 1) * 16;
    uint32_t bh_b0 = BH_OFF + (w2 * 16 + x4row) * ROWB + x4chk;
    uint32_t bh_b1 = BH_OFF + (64 + w2 * 16 + x4row) * ROWB + x4chk;
    uint32_t bl_b  = BL_OFF + (w2 * 16 + x4row) * ROWB + x4chk;

    // prologue: stage 0 and 1
    #pragma unroll
    for (int q = 0; q < 10; q++) cpasync16(sbase + soff[q], gp[q]);
    CP_COMMIT();
    #pragma unroll
    for (int q = 0; q < 10; q++) cpasync16(sbase + BUFB + soff[q], gp[q] + 64);
    CP_COMMIT();

    for (int it = 0; it < 16; it++) {
        int buf = it % 3;
        if (it + 2 < 16) {
            int k0 = (it + 2) * 64;
            uint32_t sb = sbase + ((it + 2) % 3) * BUFB;
            #pragma unroll
            for (int q = 0; q < 10; q++) cpasync16(sb + soff[q], gp[q] + k0);
            CP_COMMIT();
            asm volatile("cp.async.wait_group 2;" ::: "memory");
        } else if (it == 14) {
            asm volatile("cp.async.wait_group 1;" ::: "memory");
        } else {
            asm volatile("cp.async.wait_group 0;" ::: "memory");
        }
        __syncthreads();

        uint32_t sb = sbase + buf * BUFB;
        Frags F;
        load_frags(F, sb, 0, a_rel, bh_b0, bh_b1, bl_b);
        #pragma unroll
        for (int ks = 0; ks < 4; ks++) {
            Frags Fn;
            if (ks < 3) load_frags(Fn, sb, ks + 1, a_rel, bh_b0, bh_b1, bl_b);
            // p0: Ah * Bh (all columns)
            #pragma unroll
            for (int mt = 0; mt < 2; mt++)
                #pragma unroll
                for (int nt = 0; nt < 4; nt++)
                    mma_bf16(acc[mt][nt][0], acc[mt][nt][1], acc[mt][nt][2], acc[mt][nt][3],
                             F.ah[mt][0], F.ah[mt][1], F.ah[mt][2], F.ah[mt][3],
                             F.bh0[nt], F.bh1[nt]);
            // p1: Ah * Bl (x1 columns only)
            #pragma unroll
            for (int mt = 0; mt < 2; mt++)
                #pragma unroll
                for (int nt = 0; nt < 2; nt++)
                    mma_bf16(acc[mt][nt][0], acc[mt][nt][1], acc[mt][nt][2], acc[mt][nt][3],
                             F.ah[mt][0], F.ah[mt][1], F.ah[mt][2], F.ah[mt][3],
                             F.bl0[nt], F.bl1[nt]);
            // p2: Al * Bh (all columns)
            #pragma unroll
            for (int mt = 0; mt < 2; mt++)
                #pragma unroll
                for (int nt = 0; nt < 4; nt++)
                    mma_bf16(acc[mt][nt][0], acc[mt][nt][1], acc[mt][nt][2], acc[mt][nt][3],
                             F.al[mt][0], F.al[mt][1], F.al[mt][2], F.al[mt][3],
                             F.bh0[nt], F.bh1[nt]);
            if (ks < 3) F = Fn;
        }
        __syncthreads();
    }

    int r0 = m0 + warp_m + (lane >> 2);
    #pragma unroll
    for (int mt = 0; mt < 2; mt++) {
        #pragma unroll
        for (int nt = 0; nt < 4; nt++) {
            int cb = (nt >= 2 ? 512 : 0) + pn64 + w2 * 16 + (nt & 1) * 8 + (lane & 3) * 2;
            *(float2*)&g_U[(size_t)(r0 + mt * 16) * 1024 + cb] =
                make_float2(acc[mt][nt][0], acc[mt][nt][1]);
            *(float2*)&g_U[(size_t)(r0 + mt * 16 + 8) * 1024 + cb] =
                make_float2(acc[mt][nt][2], acc[mt][nt][3]);
        }
    }
}

// ---------------------------------------------------------------------------
// Kernel 5: pointwise epilogue (f32x2 head + piecewise-linear MLP)
// ---------------------------------------------------------------------------
__global__ __launch_bounds__(256) void epilogue_kernel(
    const float* __restrict__ x, const int* __restrict__ mask,
    const float* __restrict__ bfs, float* __restrict__ out) {
    __shared__ float s_scd[512];
    __shared__ float s_c12[256];
    __shared__ float s_r56[128];
    __shared__ float s_mt[65], s_msa[65], s_msb[65];
    int tid = threadIdx.x;
    for (int i = tid; i < 512; i += 256) s_scd[i] = g_scd[i];
    s_c12[tid] = g_c12[tid];
    if (tid < 128) s_r56[tid] = g_r56[tid];
    if (tid < 65) { s_mt[tid] = g_mt[tid]; s_msa[tid] = g_msa[tid]; s_msb[tid] = g_msb[tid]; }
    __syncthreads();
    float bfs0 = bfs[0];

    int gid = blockIdx.x * 256 + tid;
    int e = gid * 4;
    int b = e >> 16;
    int rem = e & 65535;
    int j = rem >> 6;
    int tt = rem & 63;
    int c = b * 64 + tt;

    float4 xv = *(const float4*)&x[e];
    int4 mv = *(const int4*)&mask[e];
    size_t ubase = (size_t)j * 1024 + c;
    float4 u1v = *(const float4*)&g_U[ubase];
    float4 u2v = *(const float4*)&g_U[ubase + 512];
    float sj = g_S[j];

    float x1a[4], mfa[4];
    x1a[0] = mv.x ? xv.x : bfs0; mfa[0] = (float)mv.x;
    x1a[1] = mv.y ? xv.y : bfs0; mfa[1] = (float)mv.y;
    x1a[2] = mv.z ? xv.z : bfs0; mfa[2] = (float)mv.z;
    x1a[3] = mv.w ? xv.w : bfs0; mfa[3] = (float)mv.w;

    unsigned long long x1p[2] = { pack2(x1a[0], x1a[1]), pack2(x1a[2], x1a[3]) };
    unsigned long long mfp[2] = { pack2(mfa[0], mfa[1]), pack2(mfa[2], mfa[3]) };
    unsigned long long u1p[2] = { pack2(u1v.x, u1v.y), pack2(u1v.z, u1v.w) };
    unsigned long long u2p[2] = { pack2(u2v.x, u2v.y), pack2(u2v.z, u2v.w) };

    unsigned long long acc2[2] = { 0ULL, 0ULL };
    #pragma unroll 4
    for (int h = 0; h < 64; h++) {
        ulonglong2 r12 = *(const ulonglong2*)&s_scd[h * 8];
        ulonglong2 r34 = *(const ulonglong2*)&s_scd[h * 8 + 4];
        float2 r56v = *(const float2*)&s_r56[h * 2];
        ulonglong2 cc = *(const ulonglong2*)&s_c12[h * 4];
        float base = fmaf(r56v.x, sj, r56v.y);
        unsigned long long base2 = pack2(base, base);
        #pragma unroll
        for (int q = 0; q < 2; q++) {
            unsigned long long v =
                ffma2(r12.x, x1p[q],
                ffma2(r12.y, mfp[q],
                ffma2(r34.x, u1p[q],
                ffma2(r34.y, u2p[q], base2))));
            unsigned long long av = v & 0x7fffffff7fffffffULL;
            acc2[q] = ffma2(cc.x, v, acc2[q]);
            acc2[q] = ffma2(cc.y, av, acc2[q]);
        }
    }

    float accs[4];
    { U64 p; p.u = acc2[0]; accs[0] = p.f.x; accs[1] = p.f.y; }
    { U64 p; p.u = acc2[1]; accs[2] = p.f.x; accs[3] = p.f.y; }

    float res[4];
    #pragma unroll
    for (int q = 0; q < 4; q++) {
        float xs = accs[q];
        int k = 0;
        #pragma unroll
        for (int step = 64; step > 0; step >>= 1) {
            if (k + step <= 64 && s_mt[k + step] <= xs) k += step;
        }
        res[q] = fmaf(s_msa[k], xs, s_msb[k]);
    }
    *(float4*)&out[e] = make_float4(res[0], res[1], res[2], res[3]);
}

// ---------------------------------------------------------------------------
// Launch
// ---------------------------------------------------------------------------
extern "C" void kernel_launch(void* const* d_in, const int* in_sizes, int n_in,
                              void* d_out, int out_size) {
    const float* x      = (const float*)d_in[0];
    const int*   mask   = (const int*)  d_in[1];
    const float* b_fs   = (const float*)d_in[3];
    const float* W_in   = (const float*)d_in[4];
    const float* b_in   = (const float*)d_in[5];
    const float* adj    = (const float*)d_in[6];
    const float* W_gc   = (const float*)d_in[7];
    const float* b_gc   = (const float*)d_in[8];
    const float* W_lo   = (const float*)d_in[9];
    const float* b_lo   = (const float*)d_in[10];
    const float* prelua = (const float*)d_in[11];
    const float* W_ro   = (const float*)d_in[12];
    const float* b_ro   = (const float*)d_in[13];
    const float* W_o1   = (const float*)d_in[14];
    const float* b_o1   = (const float*)d_in[15];
    const float* W_o2   = (const float*)d_in[16];
    const float* b_o2   = (const float*)d_in[17];
    float* out = (float*)d_out;

    cudaFuncSetAttribute(mma_kernel, cudaFuncAttributeMaxDynamicSharedMemorySize, MMA_SMEM);

    coef_kernel<<<1, 64>>>(W_in, b_in, W_gc, b_gc, W_lo, b_lo, W_ro, prelua,
                           W_o1, b_o1, W_o2, b_o2, b_ro);
    dim3 ga(32, 32);
    convertA_kernel<<<ga, dim3(32, 8)>>>(adj);
    dim3 gx(32, 8);
    convertX_kernel<<<gx, 256>>>(x, mask, b_fs);
    mma_kernel<<<128, 256, MMA_SMEM>>>();
    epilogue_kernel<<<ELEMS / 4 / 256, 256>>>(x, mask, b_fs, out);
}